// round 1
// baseline (speedup 1.0000x reference)
#include <cuda_runtime.h>
#include <math.h>
#include <stdint.h>

// Problem constants
constexpr int Bb = 2;
constexpr int Ss = 2048;
constexpr int Ee = 1024;
constexpr int Hh = 16;
constexpr int Dd = 64;
constexpr int NROWS = Bb * Ss;     // 4096

// Scratch (device globals — no allocation allowed)
__device__ float g_Q[(size_t)Bb * Hh * Ss * Dd];   // [B,H,S,D]
__device__ float g_K[(size_t)Bb * Hh * Ss * Dd];
__device__ float g_V[(size_t)Bb * Hh * Ss * Dd];
__device__ float g_AO[(size_t)Bb * Ss * Ee];       // [B,S,H*D] concat-head

// ---------------------------------------------------------------------------
// Kernel 1: fused QKV projection.
// C[n, h*64+d] = sum_e x[n,e] * W[h,e,d] + bias[h,d]
// Tile: BM=128, BN=64 (one head per N-tile), BK=16. 256 threads, 8x4 micro.
// ---------------------------------------------------------------------------
__global__ __launch_bounds__(256) void proj_qkv_kernel(
    const float* __restrict__ x,
    const float* __restrict__ Wq, const float* __restrict__ bq,
    const float* __restrict__ Wk, const float* __restrict__ bk,
    const float* __restrict__ Wv, const float* __restrict__ bv)
{
    __shared__ float As[16][128];  // [k][m]
    __shared__ float Bs[16][64];   // [k][d]

    const float* W; const float* bias; float* out;
    if (blockIdx.z == 0)      { W = Wq; bias = bq; out = g_Q; }
    else if (blockIdx.z == 1) { W = Wk; bias = bk; out = g_K; }
    else                      { W = Wv; bias = bv; out = g_V; }

    const int m0 = blockIdx.x * 128;
    const int n0 = blockIdx.y * 64;
    const int h  = n0 >> 6;
    const int tid = threadIdx.x;
    const int ty = tid >> 4;   // 0..15 -> rows ty + i*16
    const int tx = tid & 15;   // 0..15 -> cols tx + j*16

    const float* Wh = W + (size_t)h * Ee * Dd;

    float acc[8][4];
    #pragma unroll
    for (int i = 0; i < 8; i++)
        #pragma unroll
        for (int j = 0; j < 4; j++) acc[i][j] = 0.f;

    for (int k0 = 0; k0 < Ee; k0 += 16) {
        // Load A tile: 128 rows x 16 cols = 512 float4, 2 per thread
        #pragma unroll
        for (int i = 0; i < 2; i++) {
            int f = tid + i * 256;
            int r = f >> 2, c4 = f & 3;
            float4 v = *(const float4*)(x + (size_t)(m0 + r) * Ee + k0 + c4 * 4);
            As[c4 * 4 + 0][r] = v.x;
            As[c4 * 4 + 1][r] = v.y;
            As[c4 * 4 + 2][r] = v.z;
            As[c4 * 4 + 3][r] = v.w;
        }
        // Load B tile: 16 rows (e) x 64 cols (d) = 256 float4, 1 per thread
        {
            int rk = tid >> 4, c4 = tid & 15;
            *(float4*)(&Bs[rk][c4 * 4]) =
                *(const float4*)(Wh + (size_t)(k0 + rk) * Dd + c4 * 4);
        }
        __syncthreads();

        #pragma unroll
        for (int kk = 0; kk < 16; kk++) {
            float a[8], bb[4];
            #pragma unroll
            for (int i = 0; i < 8; i++) a[i] = As[kk][ty + i * 16];
            #pragma unroll
            for (int j = 0; j < 4; j++) bb[j] = Bs[kk][tx + j * 16];
            #pragma unroll
            for (int i = 0; i < 8; i++)
                #pragma unroll
                for (int j = 0; j < 4; j++)
                    acc[i][j] = fmaf(a[i], bb[j], acc[i][j]);
        }
        __syncthreads();
    }

    // Write out in [B,H,S,D] layout
    #pragma unroll
    for (int i = 0; i < 8; i++) {
        int n = m0 + ty + i * 16;
        int b = n >> 11, s = n & 2047;
        float* o = out + (((size_t)(b * Hh + h)) * Ss + s) * Dd;
        #pragma unroll
        for (int j = 0; j < 4; j++) {
            int d = tx + j * 16;
            o[d] = acc[i][j] + bias[h * Dd + d];
        }
    }
}

// ---------------------------------------------------------------------------
// Kernel 2: causal flash attention. One CTA per (b,h,q-tile of 64).
// 256 threads, thread (ty,tx) owns rows {ty+16i}, cols {tx+16j}, 4x4 fragment.
// ---------------------------------------------------------------------------
constexpr int ASTR = 68;  // smem row stride (floats), multiple of 4

__global__ __launch_bounds__(256) void attn_kernel()
{
    extern __shared__ float sm[];
    float* Qs  = sm;                  // [64][68]  row=q,  col=e
    float* Kts = sm + 64 * ASTR;      // [64][68]  row=e,  col=kv (transposed)
    float* Vs  = sm + 2 * 64 * ASTR;  // [64][68]  row=kv, col=d
    float* Ps  = sm + 3 * 64 * ASTR;  // [64][68]  row=q,  col=kv

    const int qt = gridDim.x - 1 - blockIdx.x;  // heavy tiles first
    const int bh = blockIdx.y;
    const int b  = bh >> 4, h = bh & 15;

    const float* Q = g_Q + (size_t)bh * Ss * Dd;
    const float* K = g_K + (size_t)bh * Ss * Dd;
    const float* V = g_V + (size_t)bh * Ss * Dd;

    const int tid = threadIdx.x;
    const int ty = tid >> 4, tx = tid & 15;
    const int q0 = qt * 64;

    // Load Q tile: 64 rows x 16 float4 = 1024 float4, 4 per thread
    #pragma unroll
    for (int i = 0; i < 4; i++) {
        int f = tid + i * 256;
        int r = f >> 4, c4 = f & 15;
        float4 v = *(const float4*)(Q + (size_t)(q0 + r) * Dd + c4 * 4);
        *(float4*)(Qs + r * ASTR + c4 * 4) = v;
    }

    float m_i[4], l_i[4], acc[4][4];
    #pragma unroll
    for (int i = 0; i < 4; i++) {
        m_i[i] = -1e30f; l_i[i] = 0.f;
        #pragma unroll
        for (int j = 0; j < 4; j++) acc[i][j] = 0.f;
    }

    const float scale = 0.125f;  // 1/sqrt(64)

    for (int t = 0; t <= qt; t++) {
        const int k0 = t * 64;
        __syncthreads();  // previous PV done reading Vs/Ps (also covers Qs fill)

        // Load K (transposed into Kts) and V tiles
        #pragma unroll
        for (int i = 0; i < 4; i++) {
            int f = tid + i * 256;
            int r = f >> 4, c4 = f & 15;
            float4 kv = *(const float4*)(K + (size_t)(k0 + r) * Dd + c4 * 4);
            Kts[(c4 * 4 + 0) * ASTR + r] = kv.x;
            Kts[(c4 * 4 + 1) * ASTR + r] = kv.y;
            Kts[(c4 * 4 + 2) * ASTR + r] = kv.z;
            Kts[(c4 * 4 + 3) * ASTR + r] = kv.w;
            float4 vv = *(const float4*)(V + (size_t)(k0 + r) * Dd + c4 * 4);
            *(float4*)(Vs + r * ASTR + c4 * 4) = vv;
        }
        __syncthreads();

        // S = Q @ K^T (4x4 fragment per thread)
        float sv[4][4];
        #pragma unroll
        for (int i = 0; i < 4; i++)
            #pragma unroll
            for (int j = 0; j < 4; j++) sv[i][j] = 0.f;

        #pragma unroll 8
        for (int e = 0; e < 64; e++) {
            float a[4], bb[4];
            #pragma unroll
            for (int i = 0; i < 4; i++) a[i] = Qs[(ty + i * 16) * ASTR + e];
            #pragma unroll
            for (int j = 0; j < 4; j++) bb[j] = Kts[e * ASTR + tx + j * 16];
            #pragma unroll
            for (int i = 0; i < 4; i++)
                #pragma unroll
                for (int j = 0; j < 4; j++)
                    sv[i][j] = fmaf(a[i], bb[j], sv[i][j]);
        }

        const bool boundary = (t == qt);

        // Online softmax per owned row
        #pragma unroll
        for (int i = 0; i < 4; i++) {
            int ri = ty + i * 16;
            float mt = -1e30f;
            #pragma unroll
            for (int j = 0; j < 4; j++) {
                float s = sv[i][j] * scale;
                if (boundary && (tx + j * 16) > ri) s = -1e30f;
                sv[i][j] = s;
                mt = fmaxf(mt, s);
            }
            // reduce max over the 16 lanes of this row group
            #pragma unroll
            for (int off = 8; off >= 1; off >>= 1)
                mt = fmaxf(mt, __shfl_xor_sync(0xffffffffu, mt, off, 16));

            float mnew = fmaxf(m_i[i], mt);
            float corr = __expf(m_i[i] - mnew);
            float rs = 0.f;
            #pragma unroll
            for (int j = 0; j < 4; j++) {
                float p = __expf(sv[i][j] - mnew);
                Ps[ri * ASTR + tx + j * 16] = p;
                rs += p;
            }
            #pragma unroll
            for (int off = 8; off >= 1; off >>= 1)
                rs += __shfl_xor_sync(0xffffffffu, rs, off, 16);

            l_i[i] = l_i[i] * corr + rs;
            m_i[i] = mnew;
            #pragma unroll
            for (int j = 0; j < 4; j++) acc[i][j] *= corr;
        }
        __syncthreads();

        // O += P @ V
        #pragma unroll 8
        for (int e = 0; e < 64; e++) {
            float p[4], v[4];
            #pragma unroll
            for (int i = 0; i < 4; i++) p[i] = Ps[(ty + i * 16) * ASTR + e];
            #pragma unroll
            for (int j = 0; j < 4; j++) v[j] = Vs[e * ASTR + tx + j * 16];
            #pragma unroll
            for (int i = 0; i < 4; i++)
                #pragma unroll
                for (int j = 0; j < 4; j++)
                    acc[i][j] = fmaf(p[i], v[j], acc[i][j]);
        }
    }

    // Normalize + write concat-head layout [B,S,H*D]
    float* dst = g_AO + (size_t)b * Ss * Ee;
    #pragma unroll
    for (int i = 0; i < 4; i++) {
        int s = q0 + ty + i * 16;
        float inv = 1.0f / l_i[i];
        #pragma unroll
        for (int j = 0; j < 4; j++)
            dst[(size_t)s * Ee + h * Dd + tx + j * 16] = acc[i][j] * inv;
    }
}

// ---------------------------------------------------------------------------
// Kernel 3: output projection. out[n,f] = sum_e AO[n,e] * Wo[e,f]
// Same tiling as kernel 1.
// ---------------------------------------------------------------------------
__global__ __launch_bounds__(256) void out_proj_kernel(
    const float* __restrict__ Wo, float* __restrict__ out)
{
    __shared__ float As[16][128];
    __shared__ float Bs[16][64];

    const int m0 = blockIdx.x * 128;
    const int n0 = blockIdx.y * 64;
    const int tid = threadIdx.x;
    const int ty = tid >> 4, tx = tid & 15;

    const float* A = g_AO;

    float acc[8][4];
    #pragma unroll
    for (int i = 0; i < 8; i++)
        #pragma unroll
        for (int j = 0; j < 4; j++) acc[i][j] = 0.f;

    for (int k0 = 0; k0 < Ee; k0 += 16) {
        #pragma unroll
        for (int i = 0; i < 2; i++) {
            int f = tid + i * 256;
            int r = f >> 2, c4 = f & 3;
            float4 v = *(const float4*)(A + (size_t)(m0 + r) * Ee + k0 + c4 * 4);
            As[c4 * 4 + 0][r] = v.x;
            As[c4 * 4 + 1][r] = v.y;
            As[c4 * 4 + 2][r] = v.z;
            As[c4 * 4 + 3][r] = v.w;
        }
        {
            int rk = tid >> 4, c4 = tid & 15;
            *(float4*)(&Bs[rk][c4 * 4]) =
                *(const float4*)(Wo + (size_t)(k0 + rk) * Ee + n0 + c4 * 4);
        }
        __syncthreads();

        #pragma unroll
        for (int kk = 0; kk < 16; kk++) {
            float a[8], bb[4];
            #pragma unroll
            for (int i = 0; i < 8; i++) a[i] = As[kk][ty + i * 16];
            #pragma unroll
            for (int j = 0; j < 4; j++) bb[j] = Bs[kk][tx + j * 16];
            #pragma unroll
            for (int i = 0; i < 8; i++)
                #pragma unroll
                for (int j = 0; j < 4; j++)
                    acc[i][j] = fmaf(a[i], bb[j], acc[i][j]);
        }
        __syncthreads();
    }

    #pragma unroll
    for (int i = 0; i < 8; i++) {
        int n = m0 + ty + i * 16;
        #pragma unroll
        for (int j = 0; j < 4; j++)
            out[(size_t)n * Ee + n0 + tx + j * 16] = acc[i][j];
    }
}

// ---------------------------------------------------------------------------
// Launch
// ---------------------------------------------------------------------------
extern "C" void kernel_launch(void* const* d_in, const int* in_sizes, int n_in,
                              void* d_out, int out_size)
{
    const float* x  = (const float*)d_in[0];
    const float* Wq = (const float*)d_in[1];
    const float* bq = (const float*)d_in[2];
    const float* Wk = (const float*)d_in[3];
    const float* bk = (const float*)d_in[4];
    const float* Wv = (const float*)d_in[5];
    const float* bv = (const float*)d_in[6];
    const float* Wo = (const float*)d_in[7];
    // d_in[8] = causal_mask (standard tril, handled analytically)
    // d_in[9] = padding_mask (all false for this problem)
    float* out = (float*)d_out;

    // QKV projections: M-tiles=4096/128=32, N-tiles=1024/64=16, z={Q,K,V}
    proj_qkv_kernel<<<dim3(32, 16, 3), 256>>>(x, Wq, bq, Wk, bk, Wv, bv);

    // Flash attention: 32 q-tiles x 32 (b,h); 68KB dynamic smem
    const int attn_smem = 4 * 64 * ASTR * (int)sizeof(float);
    cudaFuncSetAttribute(attn_kernel,
                         cudaFuncAttributeMaxDynamicSharedMemorySize, attn_smem);
    attn_kernel<<<dim3(32, Bb * Hh), 256, attn_smem>>>();

    // Output projection
    out_proj_kernel<<<dim3(32, 16), 256>>>(Wo, out);
}

// round 3
// speedup vs baseline: 1.7325x; 1.7325x over previous
#include <cuda_runtime.h>
#include <math.h>
#include <stdint.h>

// Problem constants
constexpr int Bb = 2;
constexpr int Ss = 2048;
constexpr int Ee = 1024;
constexpr int Hh = 16;
constexpr int Dd = 64;

// Scratch (device globals — no allocation allowed)
__device__ float g_Q[(size_t)Bb * Hh * Ss * Dd];   // [B,H,S,D]
__device__ float g_K[(size_t)Bb * Hh * Ss * Dd];
__device__ float g_V[(size_t)Bb * Hh * Ss * Dd];
__device__ float g_AO[(size_t)Bb * Ss * Ee];       // [B,S,H*D] concat-head

__device__ __forceinline__ uint32_t f2tf32(float f) {
    uint32_t u;
    asm("cvt.rna.tf32.f32 %0, %1;" : "=r"(u) : "f"(f));
    return u;
}

__device__ __forceinline__ void mma_tf32(float c[4], uint32_t a0, uint32_t a1,
                                         uint32_t a2, uint32_t a3,
                                         uint32_t b0, uint32_t b1) {
    asm volatile(
        "mma.sync.aligned.m16n8k8.row.col.f32.tf32.tf32.f32 "
        "{%0,%1,%2,%3}, {%4,%5,%6,%7}, {%8,%9}, {%0,%1,%2,%3};\n"
        : "+f"(c[0]), "+f"(c[1]), "+f"(c[2]), "+f"(c[3])
        : "r"(a0), "r"(a1), "r"(a2), "r"(a3), "r"(b0), "r"(b1));
}

// ---------------------------------------------------------------------------
// tf32 tensor-core GEMM, CTA tile 128x128x32, 8 warps, warp tile 64x32.
// Smem (per buffer): A[128][32] (m-major, k swizzled by k^((m&7)<<2)),
//                    B[32][128] (k-major, n swizzled by n^((k&3)<<3)).
// Both staging STS and fragment LDS are bank-conflict-free.
// ---------------------------------------------------------------------------
constexpr int BM = 128, BN = 128, BK = 32;
constexpr int A_BUF = BM * BK;   // 4096 u32
constexpr int B_BUF = BK * BN;   // 4096 u32
constexpr int GEMM_SMEM_BYTES = 2 * (A_BUF + B_BUF) * 4;  // 64 KB

struct GemmCtx {
    uint32_t* As;  // [2][128][32]
    uint32_t* Bs;  // [2][32][128]
    int tid, lane, wid, wm, wn, g, tig;
};

__device__ __forceinline__ void gemm_store_a(uint32_t* As, int buf,
                                             const float4 (&avec)[4], int tid) {
    #pragma unroll
    for (int i = 0; i < 4; i++) {
        int f = tid + i * 256;
        int r = f >> 3, c4 = f & 7;
        int kp = (4 * c4) ^ ((r & 7) << 2);
        uint32_t* p = As + buf * A_BUF + r * 32 + kp;
        p[0] = f2tf32(avec[i].x); p[1] = f2tf32(avec[i].y);
        p[2] = f2tf32(avec[i].z); p[3] = f2tf32(avec[i].w);
    }
}

__device__ __forceinline__ void gemm_store_b(uint32_t* Bs, int buf,
                                             const float4 (&bvec)[4], int tid) {
    #pragma unroll
    for (int i = 0; i < 4; i++) {
        int f = tid + i * 256;
        int kr = f >> 5, c4 = f & 31;
        int np = (4 * c4) ^ ((kr & 3) << 3);
        uint32_t* p = Bs + buf * B_BUF + kr * 128 + np;
        p[0] = f2tf32(bvec[i].x); p[1] = f2tf32(bvec[i].y);
        p[2] = f2tf32(bvec[i].z); p[3] = f2tf32(bvec[i].w);
    }
}

// One CTA-tile compute pass over smem buffer `buf`, accumulating into acc.
__device__ __forceinline__ void gemm_compute(const GemmCtx& c, int buf,
                                             float acc[4][4][4]) {
    const uint32_t* As = c.As + buf * A_BUF;
    const uint32_t* Bs = c.Bs + buf * B_BUF;
    #pragma unroll
    for (int kk = 0; kk < 4; kk++) {
        const int kb = kk * 8;
        uint32_t af[4][4];
        #pragma unroll
        for (int mt = 0; mt < 4; mt++) {
            int m = c.wm * 64 + mt * 16 + c.g;
            int sw = (c.g << 2);
            af[mt][0] = As[m * 32 + ((kb + c.tig) ^ sw)];
            af[mt][1] = As[(m + 8) * 32 + ((kb + c.tig) ^ sw)];
            af[mt][2] = As[m * 32 + ((kb + c.tig + 4) ^ sw)];
            af[mt][3] = As[(m + 8) * 32 + ((kb + c.tig + 4) ^ sw)];
        }
        uint32_t bf[4][2];
        #pragma unroll
        for (int nt = 0; nt < 4; nt++) {
            int n = c.wn * 32 + nt * 8 + c.g;
            int np = n ^ (c.tig << 3);
            bf[nt][0] = Bs[(kb + c.tig) * 128 + np];
            bf[nt][1] = Bs[(kb + c.tig + 4) * 128 + np];
        }
        #pragma unroll
        for (int mt = 0; mt < 4; mt++)
            #pragma unroll
            for (int nt = 0; nt < 4; nt++)
                mma_tf32(acc[mt][nt], af[mt][0], af[mt][1], af[mt][2], af[mt][3],
                         bf[nt][0], bf[nt][1]);
    }
}

// ---------------------------------------------------------------------------
// Kernel 1: fused QKV projection (tensor core).
// out[n, hd] = sum_e x[n,e] * W[h,e,d] + bias[h,d], written to [B,H,S,D].
// ---------------------------------------------------------------------------
__global__ __launch_bounds__(256) void proj_qkv_tc(
    const float* __restrict__ x,
    const float* __restrict__ Wq, const float* __restrict__ bq,
    const float* __restrict__ Wk, const float* __restrict__ bk,
    const float* __restrict__ Wv, const float* __restrict__ bv)
{
    extern __shared__ uint32_t sm[];
    GemmCtx c;
    c.As = sm; c.Bs = sm + 2 * A_BUF;
    c.tid = threadIdx.x; c.lane = c.tid & 31; c.wid = c.tid >> 5;
    c.wm = c.wid >> 2; c.wn = c.wid & 3;
    c.g = c.lane >> 2; c.tig = c.lane & 3;

    const float* W; const float* bias; float* out;
    if (blockIdx.z == 0)      { W = Wq; bias = bq; out = g_Q; }
    else if (blockIdx.z == 1) { W = Wk; bias = bk; out = g_K; }
    else                      { W = Wv; bias = bv; out = g_V; }

    const int m0 = blockIdx.x * BM;
    const int n0 = blockIdx.y * BN;

    float acc[4][4][4];
    #pragma unroll
    for (int mt = 0; mt < 4; mt++)
        #pragma unroll
        for (int nt = 0; nt < 4; nt++)
            #pragma unroll
            for (int v = 0; v < 4; v++) acc[mt][nt][v] = 0.f;

    // global load helpers (A: x tile; B: per-head weight gather)
    auto load_a = [&](float4 (&avec)[4], int k0) {
        #pragma unroll
        for (int i = 0; i < 4; i++) {
            int f = c.tid + i * 256;
            int r = f >> 3, c4 = f & 7;
            avec[i] = *(const float4*)(x + (size_t)(m0 + r) * Ee + k0 + c4 * 4);
        }
    };
    auto load_b = [&](float4 (&bvec)[4], int k0) {
        #pragma unroll
        for (int i = 0; i < 4; i++) {
            int f = c.tid + i * 256;
            int kr = f >> 5, c4 = f & 31;
            int col = n0 + c4 * 4;
            int h = col >> 6, d = col & 63;
            bvec[i] = *(const float4*)(W + ((size_t)h * Ee + (k0 + kr)) * Dd + d);
        }
    };

    constexpr int NK = Ee / BK;  // 32
    float4 avec[4], bvec[4];
    load_a(avec, 0); load_b(bvec, 0);
    gemm_store_a(c.As, 0, avec, c.tid);
    gemm_store_b(c.Bs, 0, bvec, c.tid);

    int buf = 0;
    for (int kt = 0; kt < NK; kt++) {
        if (kt + 1 < NK) { load_a(avec, (kt + 1) * BK); load_b(bvec, (kt + 1) * BK); }
        __syncthreads();
        gemm_compute(c, buf, acc);
        if (kt + 1 < NK) {
            gemm_store_a(c.As, buf ^ 1, avec, c.tid);
            gemm_store_b(c.Bs, buf ^ 1, bvec, c.tid);
        }
        buf ^= 1;
    }

    // Epilogue: bias + scatter to [B,H,S,D]
    #pragma unroll
    for (int mt = 0; mt < 4; mt++) {
        #pragma unroll
        for (int nt = 0; nt < 4; nt++) {
            int col = n0 + c.wn * 32 + nt * 8 + c.tig * 2;
            int h = col >> 6, d = col & 63;
            float b0 = bias[h * Dd + d], b1 = bias[h * Dd + d + 1];
            int m = m0 + c.wm * 64 + mt * 16 + c.g;
            #pragma unroll
            for (int rr = 0; rr < 2; rr++) {
                int row = m + rr * 8;
                int b = row >> 11, s = row & 2047;
                float* o = out + (((size_t)(b * Hh + h)) * Ss + s) * Dd + d;
                o[0] = acc[mt][nt][rr * 2 + 0] + b0;
                o[1] = acc[mt][nt][rr * 2 + 1] + b1;
            }
        }
    }
}

// ---------------------------------------------------------------------------
// Kernel 3: output projection (tensor core). out[n,f] = sum_e AO[n,e]*Wo[e,f]
// ---------------------------------------------------------------------------
__global__ __launch_bounds__(256) void out_proj_tc(
    const float* __restrict__ Wo, float* __restrict__ out)
{
    extern __shared__ uint32_t sm[];
    GemmCtx c;
    c.As = sm; c.Bs = sm + 2 * A_BUF;
    c.tid = threadIdx.x; c.lane = c.tid & 31; c.wid = c.tid >> 5;
    c.wm = c.wid >> 2; c.wn = c.wid & 3;
    c.g = c.lane >> 2; c.tig = c.lane & 3;

    const int m0 = blockIdx.x * BM;
    const int n0 = blockIdx.y * BN;
    const float* A = g_AO;

    float acc[4][4][4];
    #pragma unroll
    for (int mt = 0; mt < 4; mt++)
        #pragma unroll
        for (int nt = 0; nt < 4; nt++)
            #pragma unroll
            for (int v = 0; v < 4; v++) acc[mt][nt][v] = 0.f;

    auto load_a = [&](float4 (&avec)[4], int k0) {
        #pragma unroll
        for (int i = 0; i < 4; i++) {
            int f = c.tid + i * 256;
            int r = f >> 3, c4 = f & 7;
            avec[i] = *(const float4*)(A + (size_t)(m0 + r) * Ee + k0 + c4 * 4);
        }
    };
    auto load_b = [&](float4 (&bvec)[4], int k0) {
        #pragma unroll
        for (int i = 0; i < 4; i++) {
            int f = c.tid + i * 256;
            int kr = f >> 5, c4 = f & 31;
            bvec[i] = *(const float4*)(Wo + (size_t)(k0 + kr) * Ee + n0 + c4 * 4);
        }
    };

    constexpr int NK = Ee / BK;
    float4 avec[4], bvec[4];
    load_a(avec, 0); load_b(bvec, 0);
    gemm_store_a(c.As, 0, avec, c.tid);
    gemm_store_b(c.Bs, 0, bvec, c.tid);

    int buf = 0;
    for (int kt = 0; kt < NK; kt++) {
        if (kt + 1 < NK) { load_a(avec, (kt + 1) * BK); load_b(bvec, (kt + 1) * BK); }
        __syncthreads();
        gemm_compute(c, buf, acc);
        if (kt + 1 < NK) {
            gemm_store_a(c.As, buf ^ 1, avec, c.tid);
            gemm_store_b(c.Bs, buf ^ 1, bvec, c.tid);
        }
        buf ^= 1;
    }

    #pragma unroll
    for (int mt = 0; mt < 4; mt++) {
        #pragma unroll
        for (int nt = 0; nt < 4; nt++) {
            int col = n0 + c.wn * 32 + nt * 8 + c.tig * 2;
            int m = m0 + c.wm * 64 + mt * 16 + c.g;
            #pragma unroll
            for (int rr = 0; rr < 2; rr++) {
                int row = m + rr * 8;
                out[(size_t)row * Ee + col]     = acc[mt][nt][rr * 2 + 0];
                out[(size_t)row * Ee + col + 1] = acc[mt][nt][rr * 2 + 1];
            }
        }
    }
}

// ---------------------------------------------------------------------------
// Kernel 2: causal flash attention (fp32 SIMT, unchanged from R1).
// ---------------------------------------------------------------------------
constexpr int ASTR = 68;

__global__ __launch_bounds__(256) void attn_kernel()
{
    extern __shared__ float smf[];
    float* Qs  = smf;
    float* Kts = smf + 64 * ASTR;
    float* Vs  = smf + 2 * 64 * ASTR;
    float* Ps  = smf + 3 * 64 * ASTR;

    const int qt = gridDim.x - 1 - blockIdx.x;
    const int bh = blockIdx.y;
    const int b  = bh >> 4, h = bh & 15;

    const float* Q = g_Q + (size_t)bh * Ss * Dd;
    const float* K = g_K + (size_t)bh * Ss * Dd;
    const float* V = g_V + (size_t)bh * Ss * Dd;

    const int tid = threadIdx.x;
    const int ty = tid >> 4, tx = tid & 15;
    const int q0 = qt * 64;

    #pragma unroll
    for (int i = 0; i < 4; i++) {
        int f = tid + i * 256;
        int r = f >> 4, c4 = f & 15;
        float4 v = *(const float4*)(Q + (size_t)(q0 + r) * Dd + c4 * 4);
        *(float4*)(Qs + r * ASTR + c4 * 4) = v;
    }

    float m_i[4], l_i[4], acc[4][4];
    #pragma unroll
    for (int i = 0; i < 4; i++) {
        m_i[i] = -1e30f; l_i[i] = 0.f;
        #pragma unroll
        for (int j = 0; j < 4; j++) acc[i][j] = 0.f;
    }

    const float scale = 0.125f;

    for (int t = 0; t <= qt; t++) {
        const int k0 = t * 64;
        __syncthreads();

        #pragma unroll
        for (int i = 0; i < 4; i++) {
            int f = tid + i * 256;
            int r = f >> 4, c4 = f & 15;
            float4 kv = *(const float4*)(K + (size_t)(k0 + r) * Dd + c4 * 4);
            Kts[(c4 * 4 + 0) * ASTR + r] = kv.x;
            Kts[(c4 * 4 + 1) * ASTR + r] = kv.y;
            Kts[(c4 * 4 + 2) * ASTR + r] = kv.z;
            Kts[(c4 * 4 + 3) * ASTR + r] = kv.w;
            float4 vv = *(const float4*)(V + (size_t)(k0 + r) * Dd + c4 * 4);
            *(float4*)(Vs + r * ASTR + c4 * 4) = vv;
        }
        __syncthreads();

        float sv[4][4];
        #pragma unroll
        for (int i = 0; i < 4; i++)
            #pragma unroll
            for (int j = 0; j < 4; j++) sv[i][j] = 0.f;

        #pragma unroll 8
        for (int e = 0; e < 64; e++) {
            float a[4], bb[4];
            #pragma unroll
            for (int i = 0; i < 4; i++) a[i] = Qs[(ty + i * 16) * ASTR + e];
            #pragma unroll
            for (int j = 0; j < 4; j++) bb[j] = Kts[e * ASTR + tx + j * 16];
            #pragma unroll
            for (int i = 0; i < 4; i++)
                #pragma unroll
                for (int j = 0; j < 4; j++)
                    sv[i][j] = fmaf(a[i], bb[j], sv[i][j]);
        }

        const bool boundary = (t == qt);

        #pragma unroll
        for (int i = 0; i < 4; i++) {
            int ri = ty + i * 16;
            float mt = -1e30f;
            #pragma unroll
            for (int j = 0; j < 4; j++) {
                float s = sv[i][j] * scale;
                if (boundary && (tx + j * 16) > ri) s = -1e30f;
                sv[i][j] = s;
                mt = fmaxf(mt, s);
            }
            #pragma unroll
            for (int off = 8; off >= 1; off >>= 1)
                mt = fmaxf(mt, __shfl_xor_sync(0xffffffffu, mt, off, 16));

            float mnew = fmaxf(m_i[i], mt);
            float corr = __expf(m_i[i] - mnew);
            float rs = 0.f;
            #pragma unroll
            for (int j = 0; j < 4; j++) {
                float p = __expf(sv[i][j] - mnew);
                Ps[ri * ASTR + tx + j * 16] = p;
                rs += p;
            }
            #pragma unroll
            for (int off = 8; off >= 1; off >>= 1)
                rs += __shfl_xor_sync(0xffffffffu, rs, off, 16);

            l_i[i] = l_i[i] * corr + rs;
            m_i[i] = mnew;
            #pragma unroll
            for (int j = 0; j < 4; j++) acc[i][j] *= corr;
        }
        __syncthreads();

        #pragma unroll 8
        for (int e = 0; e < 64; e++) {
            float p[4], v[4];
            #pragma unroll
            for (int i = 0; i < 4; i++) p[i] = Ps[(ty + i * 16) * ASTR + e];
            #pragma unroll
            for (int j = 0; j < 4; j++) v[j] = Vs[e * ASTR + tx + j * 16];
            #pragma unroll
            for (int i = 0; i < 4; i++)
                #pragma unroll
                for (int j = 0; j < 4; j++)
                    acc[i][j] = fmaf(p[i], v[j], acc[i][j]);
        }
    }

    float* dst = g_AO + (size_t)b * Ss * Ee;
    #pragma unroll
    for (int i = 0; i < 4; i++) {
        int s = q0 + ty + i * 16;
        float inv = 1.0f / l_i[i];
        #pragma unroll
        for (int j = 0; j < 4; j++)
            dst[(size_t)s * Ee + h * Dd + tx + j * 16] = acc[i][j] * inv;
    }
}

// ---------------------------------------------------------------------------
// Launch
// ---------------------------------------------------------------------------
extern "C" void kernel_launch(void* const* d_in, const int* in_sizes, int n_in,
                              void* d_out, int out_size)
{
    const float* x  = (const float*)d_in[0];
    const float* Wq = (const float*)d_in[1];
    const float* bq = (const float*)d_in[2];
    const float* Wk = (const float*)d_in[3];
    const float* bk = (const float*)d_in[4];
    const float* Wv = (const float*)d_in[5];
    const float* bv = (const float*)d_in[6];
    const float* Wo = (const float*)d_in[7];
    float* out = (float*)d_out;

    static bool attr_set = false;
    if (!attr_set) {
        cudaFuncSetAttribute(proj_qkv_tc,
            cudaFuncAttributeMaxDynamicSharedMemorySize, GEMM_SMEM_BYTES);
        cudaFuncSetAttribute(out_proj_tc,
            cudaFuncAttributeMaxDynamicSharedMemorySize, GEMM_SMEM_BYTES);
        cudaFuncSetAttribute(attn_kernel,
            cudaFuncAttributeMaxDynamicSharedMemorySize,
            4 * 64 * ASTR * (int)sizeof(float));
        attr_set = true;
    }

    // QKV projections: 4096/128 x 1024/128 x {Q,K,V}
    proj_qkv_tc<<<dim3(32, 8, 3), 256, GEMM_SMEM_BYTES>>>(x, Wq, bq, Wk, bk, Wv, bv);

    // Flash attention
    const int attn_smem = 4 * 64 * ASTR * (int)sizeof(float);
    attn_kernel<<<dim3(32, Bb * Hh), 256, attn_smem>>>();

    // Output projection
    out_proj_tc<<<dim3(32, 8), 256, GEMM_SMEM_BYTES>>>(Wo, out);
}

// round 4
// speedup vs baseline: 2.1404x; 1.2354x over previous
#include <cuda_runtime.h>
#include <math.h>
#include <stdint.h>

// Problem constants
constexpr int Bb = 2;
constexpr int Ss = 2048;
constexpr int Ee = 1024;
constexpr int Hh = 16;
constexpr int Dd = 64;

// Scratch (device globals — no allocation allowed)
__device__ float g_Q[(size_t)Bb * Hh * Ss * Dd];   // [B,H,S,D]
__device__ float g_K[(size_t)Bb * Hh * Ss * Dd];
__device__ float g_V[(size_t)Bb * Hh * Ss * Dd];
__device__ float g_AO[(size_t)Bb * Ss * Ee];       // [B,S,H*D] concat-head

__device__ __forceinline__ uint32_t f2tf32(float f) {
    uint32_t u;
    asm("cvt.rna.tf32.f32 %0, %1;" : "=r"(u) : "f"(f));
    return u;
}

__device__ __forceinline__ void split_tf32(float x, uint32_t& hi, uint32_t& lo) {
    hi = f2tf32(x);
    float r = x - __uint_as_float(hi);
    lo = f2tf32(r);
}

__device__ __forceinline__ void mma_tf32(float c[4], uint32_t a0, uint32_t a1,
                                         uint32_t a2, uint32_t a3,
                                         uint32_t b0, uint32_t b1) {
    asm volatile(
        "mma.sync.aligned.m16n8k8.row.col.f32.tf32.tf32.f32 "
        "{%0,%1,%2,%3}, {%4,%5,%6,%7}, {%8,%9}, {%0,%1,%2,%3};\n"
        : "+f"(c[0]), "+f"(c[1]), "+f"(c[2]), "+f"(c[3])
        : "r"(a0), "r"(a1), "r"(a2), "r"(a3), "r"(b0), "r"(b1));
}

// ---------------------------------------------------------------------------
// 3xTF32 tensor-core GEMM, CTA tile 128x128x32, 8 warps, warp tile 64x32.
// hi/lo split restores ~fp32 accuracy: acc += Ah*Bh + Ah*Bl + Al*Bh.
// Smem per (buf,sel): A[128][32] (k swizzled by ^((m&7)<<2)),
//                     B[32][128] (n swizzled by ^((k&3)<<3)).
// ---------------------------------------------------------------------------
constexpr int BM = 128, BN = 128, BK = 32;
constexpr int A_BUF = BM * BK;   // 4096 u32
constexpr int B_BUF = BK * BN;   // 4096 u32
// layout: A_hi[2], A_lo[2], B_hi[2], B_lo[2]
constexpr int GEMM_SMEM_BYTES = 4 * (A_BUF + B_BUF) * 4;  // 128 KB

struct GemmCtx {
    uint32_t* As;  // base of A region (hi buf0, hi buf1, lo buf0, lo buf1)
    uint32_t* Bs;
    int tid, lane, wid, wm, wn, g, tig;
};

__device__ __forceinline__ void gemm_store_a(uint32_t* As, int buf,
                                             const float4 (&avec)[4], int tid) {
    #pragma unroll
    for (int i = 0; i < 4; i++) {
        int f = tid + i * 256;
        int r = f >> 3, c4 = f & 7;
        int kp = (4 * c4) ^ ((r & 7) << 2);
        uint32_t* ph = As + buf * A_BUF + r * 32 + kp;
        uint32_t* pl = ph + 2 * A_BUF;
        uint4 h, l;
        split_tf32(avec[i].x, h.x, l.x);
        split_tf32(avec[i].y, h.y, l.y);
        split_tf32(avec[i].z, h.z, l.z);
        split_tf32(avec[i].w, h.w, l.w);
        *(uint4*)ph = h;
        *(uint4*)pl = l;
    }
}

__device__ __forceinline__ void gemm_store_b(uint32_t* Bs, int buf,
                                             const float4 (&bvec)[4], int tid) {
    #pragma unroll
    for (int i = 0; i < 4; i++) {
        int f = tid + i * 256;
        int kr = f >> 5, c4 = f & 31;
        int np = (4 * c4) ^ ((kr & 3) << 3);
        uint32_t* ph = Bs + buf * B_BUF + kr * 128 + np;
        uint32_t* pl = ph + 2 * B_BUF;
        uint4 h, l;
        split_tf32(bvec[i].x, h.x, l.x);
        split_tf32(bvec[i].y, h.y, l.y);
        split_tf32(bvec[i].z, h.z, l.z);
        split_tf32(bvec[i].w, h.w, l.w);
        *(uint4*)ph = h;
        *(uint4*)pl = l;
    }
}

__device__ __forceinline__ void gemm_compute3(const GemmCtx& c, int buf,
                                              float acc[4][4][4]) {
    const uint32_t* Ah = c.As + buf * A_BUF;
    const uint32_t* Al = Ah + 2 * A_BUF;
    const uint32_t* Bh = c.Bs + buf * B_BUF;
    const uint32_t* Bl = Bh + 2 * B_BUF;
    #pragma unroll
    for (int kk = 0; kk < 4; kk++) {
        const int kb = kk * 8;
        uint32_t bh_[4][2], bl_[4][2];
        #pragma unroll
        for (int nt = 0; nt < 4; nt++) {
            int n = c.wn * 32 + nt * 8 + c.g;
            int np = n ^ (c.tig << 3);
            bh_[nt][0] = Bh[(kb + c.tig) * 128 + np];
            bh_[nt][1] = Bh[(kb + c.tig + 4) * 128 + np];
            bl_[nt][0] = Bl[(kb + c.tig) * 128 + np];
            bl_[nt][1] = Bl[(kb + c.tig + 4) * 128 + np];
        }
        #pragma unroll
        for (int mt = 0; mt < 4; mt++) {
            int m = c.wm * 64 + mt * 16 + c.g;
            int sw = (c.g << 2);
            int k0 = (kb + c.tig) ^ sw, k1 = (kb + c.tig + 4) ^ sw;
            uint32_t ah0 = Ah[m * 32 + k0], ah1 = Ah[(m + 8) * 32 + k0];
            uint32_t ah2 = Ah[m * 32 + k1], ah3 = Ah[(m + 8) * 32 + k1];
            uint32_t al0 = Al[m * 32 + k0], al1 = Al[(m + 8) * 32 + k0];
            uint32_t al2 = Al[m * 32 + k1], al3 = Al[(m + 8) * 32 + k1];
            #pragma unroll
            for (int nt = 0; nt < 4; nt++) {
                mma_tf32(acc[mt][nt], ah0, ah1, ah2, ah3, bh_[nt][0], bh_[nt][1]);
                mma_tf32(acc[mt][nt], ah0, ah1, ah2, ah3, bl_[nt][0], bl_[nt][1]);
                mma_tf32(acc[mt][nt], al0, al1, al2, al3, bh_[nt][0], bh_[nt][1]);
            }
        }
    }
}

// ---------------------------------------------------------------------------
// Kernel 1: fused QKV projection (3xTF32 tensor core).
// ---------------------------------------------------------------------------
__global__ __launch_bounds__(256, 1) void proj_qkv_tc(
    const float* __restrict__ x,
    const float* __restrict__ Wq, const float* __restrict__ bq,
    const float* __restrict__ Wk, const float* __restrict__ bk,
    const float* __restrict__ Wv, const float* __restrict__ bv)
{
    extern __shared__ uint32_t sm[];
    GemmCtx c;
    c.As = sm; c.Bs = sm + 4 * A_BUF;
    c.tid = threadIdx.x; c.lane = c.tid & 31; c.wid = c.tid >> 5;
    c.wm = c.wid >> 2; c.wn = c.wid & 3;
    c.g = c.lane >> 2; c.tig = c.lane & 3;

    const float* W; const float* bias; float* out;
    if (blockIdx.z == 0)      { W = Wq; bias = bq; out = g_Q; }
    else if (blockIdx.z == 1) { W = Wk; bias = bk; out = g_K; }
    else                      { W = Wv; bias = bv; out = g_V; }

    const int m0 = blockIdx.x * BM;
    const int n0 = blockIdx.y * BN;

    float acc[4][4][4];
    #pragma unroll
    for (int mt = 0; mt < 4; mt++)
        #pragma unroll
        for (int nt = 0; nt < 4; nt++)
            #pragma unroll
            for (int v = 0; v < 4; v++) acc[mt][nt][v] = 0.f;

    auto load_a = [&](float4 (&avec)[4], int k0) {
        #pragma unroll
        for (int i = 0; i < 4; i++) {
            int f = c.tid + i * 256;
            int r = f >> 3, c4 = f & 7;
            avec[i] = *(const float4*)(x + (size_t)(m0 + r) * Ee + k0 + c4 * 4);
        }
    };
    auto load_b = [&](float4 (&bvec)[4], int k0) {
        #pragma unroll
        for (int i = 0; i < 4; i++) {
            int f = c.tid + i * 256;
            int kr = f >> 5, c4 = f & 31;
            int col = n0 + c4 * 4;
            int h = col >> 6, d = col & 63;
            bvec[i] = *(const float4*)(W + ((size_t)h * Ee + (k0 + kr)) * Dd + d);
        }
    };

    constexpr int NK = Ee / BK;  // 32
    float4 avec[4], bvec[4];
    load_a(avec, 0); load_b(bvec, 0);
    gemm_store_a(c.As, 0, avec, c.tid);
    gemm_store_b(c.Bs, 0, bvec, c.tid);

    int buf = 0;
    for (int kt = 0; kt < NK; kt++) {
        if (kt + 1 < NK) { load_a(avec, (kt + 1) * BK); load_b(bvec, (kt + 1) * BK); }
        __syncthreads();
        gemm_compute3(c, buf, acc);
        if (kt + 1 < NK) {
            gemm_store_a(c.As, buf ^ 1, avec, c.tid);
            gemm_store_b(c.Bs, buf ^ 1, bvec, c.tid);
        }
        buf ^= 1;
    }

    // Epilogue: bias + scatter to [B,H,S,D]
    #pragma unroll
    for (int mt = 0; mt < 4; mt++) {
        #pragma unroll
        for (int nt = 0; nt < 4; nt++) {
            int col = n0 + c.wn * 32 + nt * 8 + c.tig * 2;
            int h = col >> 6, d = col & 63;
            float b0 = bias[h * Dd + d], b1 = bias[h * Dd + d + 1];
            int m = m0 + c.wm * 64 + mt * 16 + c.g;
            #pragma unroll
            for (int rr = 0; rr < 2; rr++) {
                int row = m + rr * 8;
                int b = row >> 11, s = row & 2047;
                float* o = out + (((size_t)(b * Hh + h)) * Ss + s) * Dd + d;
                o[0] = acc[mt][nt][rr * 2 + 0] + b0;
                o[1] = acc[mt][nt][rr * 2 + 1] + b1;
            }
        }
    }
}

// ---------------------------------------------------------------------------
// Kernel 3: output projection (3xTF32 tensor core).
// ---------------------------------------------------------------------------
__global__ __launch_bounds__(256, 1) void out_proj_tc(
    const float* __restrict__ Wo, float* __restrict__ out)
{
    extern __shared__ uint32_t sm[];
    GemmCtx c;
    c.As = sm; c.Bs = sm + 4 * A_BUF;
    c.tid = threadIdx.x; c.lane = c.tid & 31; c.wid = c.tid >> 5;
    c.wm = c.wid >> 2; c.wn = c.wid & 3;
    c.g = c.lane >> 2; c.tig = c.lane & 3;

    const int m0 = blockIdx.x * BM;
    const int n0 = blockIdx.y * BN;
    const float* A = g_AO;

    float acc[4][4][4];
    #pragma unroll
    for (int mt = 0; mt < 4; mt++)
        #pragma unroll
        for (int nt = 0; nt < 4; nt++)
            #pragma unroll
            for (int v = 0; v < 4; v++) acc[mt][nt][v] = 0.f;

    auto load_a = [&](float4 (&avec)[4], int k0) {
        #pragma unroll
        for (int i = 0; i < 4; i++) {
            int f = c.tid + i * 256;
            int r = f >> 3, c4 = f & 7;
            avec[i] = *(const float4*)(A + (size_t)(m0 + r) * Ee + k0 + c4 * 4);
        }
    };
    auto load_b = [&](float4 (&bvec)[4], int k0) {
        #pragma unroll
        for (int i = 0; i < 4; i++) {
            int f = c.tid + i * 256;
            int kr = f >> 5, c4 = f & 31;
            bvec[i] = *(const float4*)(Wo + (size_t)(k0 + kr) * Ee + n0 + c4 * 4);
        }
    };

    constexpr int NK = Ee / BK;
    float4 avec[4], bvec[4];
    load_a(avec, 0); load_b(bvec, 0);
    gemm_store_a(c.As, 0, avec, c.tid);
    gemm_store_b(c.Bs, 0, bvec, c.tid);

    int buf = 0;
    for (int kt = 0; kt < NK; kt++) {
        if (kt + 1 < NK) { load_a(avec, (kt + 1) * BK); load_b(bvec, (kt + 1) * BK); }
        __syncthreads();
        gemm_compute3(c, buf, acc);
        if (kt + 1 < NK) {
            gemm_store_a(c.As, buf ^ 1, avec, c.tid);
            gemm_store_b(c.Bs, buf ^ 1, bvec, c.tid);
        }
        buf ^= 1;
    }

    #pragma unroll
    for (int mt = 0; mt < 4; mt++) {
        #pragma unroll
        for (int nt = 0; nt < 4; nt++) {
            int col = n0 + c.wn * 32 + nt * 8 + c.tig * 2;
            int m = m0 + c.wm * 64 + mt * 16 + c.g;
            #pragma unroll
            for (int rr = 0; rr < 2; rr++) {
                int row = m + rr * 8;
                out[(size_t)row * Ee + col]     = acc[mt][nt][rr * 2 + 0];
                out[(size_t)row * Ee + col + 1] = acc[mt][nt][rr * 2 + 1];
            }
        }
    }
}

// ---------------------------------------------------------------------------
// Kernel 2: causal flash attention, tf32 tensor cores.
// CTA = 128 q rows (8 warps x 16), KV tiles of 64. Q frags in registers.
// K,V consumed as B operand from NATURAL [kv][d] smem layout (no transpose):
//   Ks stride 68 -> B-frag banks 4g+tig (conflict-free)
//   Vs stride 72 -> B-frag banks 8tig+g (conflict-free)
// P staged per-warp in smem (stride 68 -> A-frag banks 4g+tig).
// ---------------------------------------------------------------------------
constexpr int PSTR = 68;
constexpr int KSTR = 68;
constexpr int VSTR = 72;
constexpr int ATTN_SMEM_BYTES = (128 * PSTR + 64 * KSTR + 64 * VSTR) * 4; // 70656

__global__ __launch_bounds__(256, 1) void attn_tc()
{
    extern __shared__ uint32_t smu[];
    uint32_t* Ps = smu;                       // [128][68] (Q stage, then P)
    uint32_t* Ks = smu + 128 * PSTR;          // [64][68]
    uint32_t* Vs = Ks + 64 * KSTR;            // [64][72]

    const int qt = 15 - (int)blockIdx.x;      // heavy q-tiles first
    const int bh = blockIdx.y;
    const int q0 = qt * 128;
    const int ntiles = 2 * qt + 2;

    const float* Qg = g_Q + (size_t)bh * Ss * Dd;
    const float* Kg = g_K + (size_t)bh * Ss * Dd;
    const float* Vg = g_V + (size_t)bh * Ss * Dd;

    const int tid = threadIdx.x;
    const int lane = tid & 31;
    const int w = tid >> 5;
    const int g = lane >> 2;
    const int tig = lane & 3;
    const int w16 = w * 16;

    // Stage Q tile (tf32) into Ps
    #pragma unroll
    for (int i = 0; i < 8; i++) {
        int f = tid + i * 256;
        int r = f >> 4, c4 = f & 15;
        float4 v = *(const float4*)(Qg + (size_t)(q0 + r) * Dd + c4 * 4);
        uint4 u = make_uint4(f2tf32(v.x), f2tf32(v.y), f2tf32(v.z), f2tf32(v.w));
        *(uint4*)(Ps + r * PSTR + c4 * 4) = u;
    }
    // Stage K/V tile 0
    #pragma unroll
    for (int i = 0; i < 4; i++) {
        int f = tid + i * 256;
        int r = f >> 4, c4 = f & 15;
        float4 kv = *(const float4*)(Kg + (size_t)r * Dd + c4 * 4);
        *(uint4*)(Ks + r * KSTR + c4 * 4) =
            make_uint4(f2tf32(kv.x), f2tf32(kv.y), f2tf32(kv.z), f2tf32(kv.w));
        float4 vv = *(const float4*)(Vg + (size_t)r * Dd + c4 * 4);
        *(uint4*)(Vs + r * VSTR + c4 * 4) =
            make_uint4(f2tf32(vv.x), f2tf32(vv.y), f2tf32(vv.z), f2tf32(vv.w));
    }
    __syncthreads();

    // Extract Q fragments (each warp reads only its own 16 rows)
    uint32_t qf[8][4];
    #pragma unroll
    for (int kk = 0; kk < 8; kk++) {
        qf[kk][0] = Ps[(w16 + g) * PSTR + kk * 8 + tig];
        qf[kk][1] = Ps[(w16 + g + 8) * PSTR + kk * 8 + tig];
        qf[kk][2] = Ps[(w16 + g) * PSTR + kk * 8 + tig + 4];
        qf[kk][3] = Ps[(w16 + g + 8) * PSTR + kk * 8 + tig + 4];
    }

    float oacc[8][4];
    #pragma unroll
    for (int nf = 0; nf < 8; nf++)
        #pragma unroll
        for (int v = 0; v < 4; v++) oacc[nf][v] = 0.f;
    float mrow[2] = {-1e30f, -1e30f};
    float lrow[2] = {0.f, 0.f};
    const float scale = 0.125f;

    for (int t = 0; t < ntiles; t++) {
        // S = Q @ K^T
        float sacc[8][4];
        #pragma unroll
        for (int nf = 0; nf < 8; nf++)
            #pragma unroll
            for (int v = 0; v < 4; v++) sacc[nf][v] = 0.f;

        #pragma unroll
        for (int kk = 0; kk < 8; kk++) {
            #pragma unroll
            for (int nf = 0; nf < 8; nf++) {
                uint32_t b0 = Ks[(nf * 8 + g) * KSTR + kk * 8 + tig];
                uint32_t b1 = Ks[(nf * 8 + g) * KSTR + kk * 8 + tig + 4];
                mma_tf32(sacc[nf], qf[kk][0], qf[kk][1], qf[kk][2], qf[kk][3],
                         b0, b1);
            }
        }

        const int kv0 = t * 64;
        const bool domask = (t >= ntiles - 2);

        // Online softmax on register fragments
        #pragma unroll
        for (int r = 0; r < 2; r++) {
            const int rowg = q0 + w16 + g + 8 * r;
            float mt = -1e30f;
            #pragma unroll
            for (int nf = 0; nf < 8; nf++) {
                float s0 = sacc[nf][2 * r]     * scale;
                float s1 = sacc[nf][2 * r + 1] * scale;
                if (domask) {
                    int col = kv0 + nf * 8 + 2 * tig;
                    if (col > rowg)     s0 = -1e30f;
                    if (col + 1 > rowg) s1 = -1e30f;
                }
                sacc[nf][2 * r] = s0; sacc[nf][2 * r + 1] = s1;
                mt = fmaxf(mt, fmaxf(s0, s1));
            }
            mt = fmaxf(mt, __shfl_xor_sync(0xffffffffu, mt, 1, 4));
            mt = fmaxf(mt, __shfl_xor_sync(0xffffffffu, mt, 2, 4));
            float mnew = fmaxf(mrow[r], mt);
            float corr = __expf(mrow[r] - mnew);
            float rs = 0.f;
            #pragma unroll
            for (int nf = 0; nf < 8; nf++) {
                float p0 = __expf(sacc[nf][2 * r] - mnew);
                float p1 = __expf(sacc[nf][2 * r + 1] - mnew);
                rs += p0 + p1;
                uint32_t* pp = Ps + (w16 + g + 8 * r) * PSTR + nf * 8 + 2 * tig;
                pp[0] = f2tf32(p0); pp[1] = f2tf32(p1);
            }
            rs += __shfl_xor_sync(0xffffffffu, rs, 1, 4);
            rs += __shfl_xor_sync(0xffffffffu, rs, 2, 4);
            lrow[r] = lrow[r] * corr + rs;
            mrow[r] = mnew;
            #pragma unroll
            for (int nf = 0; nf < 8; nf++) {
                oacc[nf][2 * r]     *= corr;
                oacc[nf][2 * r + 1] *= corr;
            }
        }
        __syncwarp();

        // O += P @ V
        #pragma unroll
        for (int kk = 0; kk < 8; kk++) {
            uint32_t a0 = Ps[(w16 + g) * PSTR + kk * 8 + tig];
            uint32_t a1 = Ps[(w16 + g + 8) * PSTR + kk * 8 + tig];
            uint32_t a2 = Ps[(w16 + g) * PSTR + kk * 8 + tig + 4];
            uint32_t a3 = Ps[(w16 + g + 8) * PSTR + kk * 8 + tig + 4];
            #pragma unroll
            for (int nf = 0; nf < 8; nf++) {
                uint32_t b0 = Vs[(kk * 8 + tig) * VSTR + nf * 8 + g];
                uint32_t b1 = Vs[(kk * 8 + tig + 4) * VSTR + nf * 8 + g];
                mma_tf32(oacc[nf], a0, a1, a2, a3, b0, b1);
            }
        }

        // Stage next K/V tile
        if (t + 1 < ntiles) {
            __syncthreads();
            const int k0n = (t + 1) * 64;
            #pragma unroll
            for (int i = 0; i < 4; i++) {
                int f = tid + i * 256;
                int r2 = f >> 4, c4 = f & 15;
                float4 kv = *(const float4*)(Kg + (size_t)(k0n + r2) * Dd + c4 * 4);
                *(uint4*)(Ks + r2 * KSTR + c4 * 4) =
                    make_uint4(f2tf32(kv.x), f2tf32(kv.y), f2tf32(kv.z), f2tf32(kv.w));
                float4 vv = *(const float4*)(Vg + (size_t)(k0n + r2) * Dd + c4 * 4);
                *(uint4*)(Vs + r2 * VSTR + c4 * 4) =
                    make_uint4(f2tf32(vv.x), f2tf32(vv.y), f2tf32(vv.z), f2tf32(vv.w));
            }
            __syncthreads();
        }
    }

    // Epilogue: normalize + write concat-head layout [B,S,H*D]
    const int b = bh >> 4, h = bh & 15;
    float* dst = g_AO + (size_t)b * Ss * Ee + h * Dd;
    #pragma unroll
    for (int r = 0; r < 2; r++) {
        float inv = 1.0f / lrow[r];
        int s = q0 + w16 + g + 8 * r;
        #pragma unroll
        for (int nf = 0; nf < 8; nf++) {
            int d = nf * 8 + 2 * tig;
            dst[(size_t)s * Ee + d]     = oacc[nf][2 * r]     * inv;
            dst[(size_t)s * Ee + d + 1] = oacc[nf][2 * r + 1] * inv;
        }
    }
}

// ---------------------------------------------------------------------------
// Launch
// ---------------------------------------------------------------------------
extern "C" void kernel_launch(void* const* d_in, const int* in_sizes, int n_in,
                              void* d_out, int out_size)
{
    const float* x  = (const float*)d_in[0];
    const float* Wq = (const float*)d_in[1];
    const float* bq = (const float*)d_in[2];
    const float* Wk = (const float*)d_in[3];
    const float* bk = (const float*)d_in[4];
    const float* Wv = (const float*)d_in[5];
    const float* bv = (const float*)d_in[6];
    const float* Wo = (const float*)d_in[7];
    float* out = (float*)d_out;

    static bool attr_set = false;
    if (!attr_set) {
        cudaFuncSetAttribute(proj_qkv_tc,
            cudaFuncAttributeMaxDynamicSharedMemorySize, GEMM_SMEM_BYTES);
        cudaFuncSetAttribute(out_proj_tc,
            cudaFuncAttributeMaxDynamicSharedMemorySize, GEMM_SMEM_BYTES);
        cudaFuncSetAttribute(attn_tc,
            cudaFuncAttributeMaxDynamicSharedMemorySize, ATTN_SMEM_BYTES);
        attr_set = true;
    }

    // QKV projections: 4096/128 x 1024/128 x {Q,K,V}
    proj_qkv_tc<<<dim3(32, 8, 3), 256, GEMM_SMEM_BYTES>>>(x, Wq, bq, Wk, bk, Wv, bv);

    // Flash attention: 16 q-tiles x 32 (b,h)
    attn_tc<<<dim3(16, Bb * Hh), 256, ATTN_SMEM_BYTES>>>();

    // Output projection
    out_proj_tc<<<dim3(32, 8), 256, GEMM_SMEM_BYTES>>>(Wo, out);
}

// round 5
// speedup vs baseline: 2.9232x; 1.3657x over previous
#include <cuda_runtime.h>
#include <cuda_bf16.h>
#include <math.h>
#include <stdint.h>

// Problem constants
constexpr int Bb = 2;
constexpr int Ss = 2048;
constexpr int Ee = 1024;
constexpr int Hh = 16;
constexpr int Dd = 64;

// Scratch (device globals — no allocation allowed)
__device__ float g_Q[(size_t)Bb * Hh * Ss * Dd];   // [B,H,S,D]
__device__ float g_K[(size_t)Bb * Hh * Ss * Dd];
__device__ float g_V[(size_t)Bb * Hh * Ss * Dd];
__device__ float g_AO[(size_t)Bb * Ss * Ee];       // [B,S,H*D] concat-head
// Pre-packed weights, bf16 hi/lo, layout [z][n][kp] (kp = k/2, u32 = 2 bf16)
// z: 0=Wq, 1=Wk, 2=Wv, 3=Wo
__device__ uint32_t g_Wh[(size_t)4 * Ee * (Ee / 2)];
__device__ uint32_t g_Wl[(size_t)4 * Ee * (Ee / 2)];

// ---------------------------------------------------------------------------
// Helpers
// ---------------------------------------------------------------------------
__device__ __forceinline__ uint32_t f2tf32(float f) {
    uint32_t u;
    asm("cvt.rna.tf32.f32 %0, %1;" : "=r"(u) : "f"(f));
    return u;
}

// pack two floats into bf16x2: low 16 bits = e_even, high = e_odd
__device__ __forceinline__ uint32_t pack_bf16x2(float e_even, float e_odd) {
    uint32_t r;
    asm("cvt.rn.bf16x2.f32 %0, %1, %2;" : "=r"(r) : "f"(e_odd), "f"(e_even));
    return r;
}

// split (v0, v1) into hi/lo bf16x2 pairs
__device__ __forceinline__ void split2(float v0, float v1,
                                       uint32_t& hi, uint32_t& lo) {
    float h0 = __bfloat162float(__float2bfloat16(v0));
    float h1 = __bfloat162float(__float2bfloat16(v1));
    hi = pack_bf16x2(h0, h1);
    lo = pack_bf16x2(v0 - h0, v1 - h1);
}

__device__ __forceinline__ void mma_tf32(float c[4], uint32_t a0, uint32_t a1,
                                         uint32_t a2, uint32_t a3,
                                         uint32_t b0, uint32_t b1) {
    asm volatile(
        "mma.sync.aligned.m16n8k8.row.col.f32.tf32.tf32.f32 "
        "{%0,%1,%2,%3}, {%4,%5,%6,%7}, {%8,%9}, {%0,%1,%2,%3};\n"
        : "+f"(c[0]), "+f"(c[1]), "+f"(c[2]), "+f"(c[3])
        : "r"(a0), "r"(a1), "r"(a2), "r"(a3), "r"(b0), "r"(b1));
}

__device__ __forceinline__ void mma_bf16(float c[4], uint32_t a0, uint32_t a1,
                                         uint32_t a2, uint32_t a3,
                                         uint32_t b0, uint32_t b1) {
    asm volatile(
        "mma.sync.aligned.m16n8k16.row.col.f32.bf16.bf16.f32 "
        "{%0,%1,%2,%3}, {%4,%5,%6,%7}, {%8,%9}, {%0,%1,%2,%3};\n"
        : "+f"(c[0]), "+f"(c[1]), "+f"(c[2]), "+f"(c[3])
        : "r"(a0), "r"(a1), "r"(a2), "r"(a3), "r"(b0), "r"(b1));
}

// ---------------------------------------------------------------------------
// Kernel 0: weight pre-pack. Transpose W to [n][kpair], split bf16 hi/lo.
// grid (32 k-tiles, 32 n-tiles, 4 matrices), block 256.
// ---------------------------------------------------------------------------
__global__ __launch_bounds__(256) void prep_pack(
    const float* __restrict__ Wq, const float* __restrict__ Wk,
    const float* __restrict__ Wv, const float* __restrict__ Wo)
{
    __shared__ float t[32][33];
    const int k0 = blockIdx.x * 32, n0 = blockIdx.y * 32;
    const int z = blockIdx.z;
    const float* W = (z == 0) ? Wq : (z == 1) ? Wk : (z == 2) ? Wv : Wo;
    const int tid = threadIdx.x;

    #pragma unroll
    for (int it = 0; it < 4; it++) {
        int idx = tid + it * 256;
        int kk = idx >> 5, nn = idx & 31;
        float v;
        if (z < 3) {
            // W is [H][E][D]; column n = h*64 + d ; 32-wide n-tile never
            // crosses a head boundary (n0 is 32-aligned).
            int n = n0 + nn, h = n >> 6, d = n & 63;
            v = W[((size_t)h * Ee + (k0 + kk)) * Dd + d];
        } else {
            v = W[(size_t)(k0 + kk) * Ee + (n0 + nn)];
        }
        t[kk][nn] = v;
    }
    __syncthreads();

    uint32_t* hi = g_Wh + (size_t)z * Ee * (Ee / 2);
    uint32_t* lo = g_Wl + (size_t)z * Ee * (Ee / 2);
    #pragma unroll
    for (int it = 0; it < 2; it++) {
        int idx = tid + it * 256;
        int nn = idx >> 4, kp = idx & 15;
        uint32_t h, l;
        split2(t[2 * kp][nn], t[2 * kp + 1][nn], h, l);
        size_t o = (size_t)(n0 + nn) * (Ee / 2) + (k0 >> 1) + kp;
        hi[o] = h; lo[o] = l;
    }
}

// ---------------------------------------------------------------------------
// 2-split bf16 tensor-core GEMM, CTA tile 128x128x32, 8 warps (64x32 warp
// tile), m16n8k16. acc += Ah*Bh + Ah*Bl + Al*Bh (Al*Bl ~2^-18, dropped).
// Smem: u32-packed bf16 pairs, row stride 20 u32 -> conflict-free frag LDS.
//   A region: [hi buf0][hi buf1][lo buf0][lo buf1], each 128x20 u32
//   B region: same, rows = n
// ---------------------------------------------------------------------------
constexpr int BM = 128, BN = 128, BK = 32;
constexpr int PSTRIDE = 20;               // u32 per packed row
constexpr int PBUF = 128 * PSTRIDE;       // 2560 u32 per (sel, buf)
constexpr int GEMM_SMEM_BYTES = 8 * PBUF * 4;  // A(4) + B(4) = 81920 B

struct GemmCtx {
    uint32_t* As;   // A region base
    uint32_t* Bs;   // B region base
    int tid, lane, wid, wm, wn, g, tig;
};

// Stage A tile (fp32 -> split bf16 pairs). avec = 4 float4 per thread.
__device__ __forceinline__ void stage_a(uint32_t* As, int buf,
                                        const float4 (&avec)[4], int tid) {
    #pragma unroll
    for (int i = 0; i < 4; i++) {
        int f = tid + i * 256;
        int m = f >> 3, c4 = f & 7;          // kp base = c4*2
        uint32_t h0, l0, h1, l1;
        split2(avec[i].x, avec[i].y, h0, l0);
        split2(avec[i].z, avec[i].w, h1, l1);
        uint32_t* ph = As + buf * PBUF + m * PSTRIDE + c4 * 2;
        uint32_t* pl = ph + 2 * PBUF;
        *(uint2*)ph = make_uint2(h0, h1);
        *(uint2*)pl = make_uint2(l0, l1);
    }
}

// Stage B tile (already packed in global). bh/bl = 2 uint4 each per thread.
__device__ __forceinline__ void stage_b(uint32_t* Bs, int buf,
                                        const uint4 (&bh)[2],
                                        const uint4 (&bl)[2], int tid) {
    #pragma unroll
    for (int i = 0; i < 2; i++) {
        int f = tid + i * 256;
        int n = f >> 2, c4 = f & 3;
        uint32_t* ph = Bs + buf * PBUF + n * PSTRIDE + c4 * 4;
        uint32_t* pl = ph + 2 * PBUF;
        *(uint4*)ph = bh[i];
        *(uint4*)pl = bl[i];
    }
}

__device__ __forceinline__ void gemm_compute_bf16(const GemmCtx& c, int buf,
                                                  float acc[4][4][4]) {
    const uint32_t* Ah = c.As + buf * PBUF;
    const uint32_t* Al = Ah + 2 * PBUF;
    const uint32_t* Bh = c.Bs + buf * PBUF;
    const uint32_t* Bl = Bh + 2 * PBUF;
    #pragma unroll
    for (int s = 0; s < 2; s++) {            // two k16 steps per BK=32
        const int cb = 8 * s;
        uint32_t bh_[4][2], bl_[4][2];
        #pragma unroll
        for (int nt = 0; nt < 4; nt++) {
            int n = c.wn * 32 + nt * 8 + c.g;
            bh_[nt][0] = Bh[n * PSTRIDE + cb + c.tig];
            bh_[nt][1] = Bh[n * PSTRIDE + cb + c.tig + 4];
            bl_[nt][0] = Bl[n * PSTRIDE + cb + c.tig];
            bl_[nt][1] = Bl[n * PSTRIDE + cb + c.tig + 4];
        }
        #pragma unroll
        for (int mt = 0; mt < 4; mt++) {
            int r0 = c.wm * 64 + mt * 16 + c.g, r1 = r0 + 8;
            uint32_t ah0 = Ah[r0 * PSTRIDE + cb + c.tig];
            uint32_t ah1 = Ah[r1 * PSTRIDE + cb + c.tig];
            uint32_t ah2 = Ah[r0 * PSTRIDE + cb + c.tig + 4];
            uint32_t ah3 = Ah[r1 * PSTRIDE + cb + c.tig + 4];
            uint32_t al0 = Al[r0 * PSTRIDE + cb + c.tig];
            uint32_t al1 = Al[r1 * PSTRIDE + cb + c.tig];
            uint32_t al2 = Al[r0 * PSTRIDE + cb + c.tig + 4];
            uint32_t al3 = Al[r1 * PSTRIDE + cb + c.tig + 4];
            #pragma unroll
            for (int nt = 0; nt < 4; nt++) {
                mma_bf16(acc[mt][nt], ah0, ah1, ah2, ah3, bh_[nt][0], bh_[nt][1]);
                mma_bf16(acc[mt][nt], ah0, ah1, ah2, ah3, bl_[nt][0], bl_[nt][1]);
                mma_bf16(acc[mt][nt], al0, al1, al2, al3, bh_[nt][0], bh_[nt][1]);
            }
        }
    }
}

// ---------------------------------------------------------------------------
// Kernel 1: fused QKV projection (2-split bf16 tensor core).
// ---------------------------------------------------------------------------
__global__ __launch_bounds__(256, 1) void proj_qkv_tc(
    const float* __restrict__ x,
    const float* __restrict__ bq, const float* __restrict__ bk,
    const float* __restrict__ bv)
{
    extern __shared__ uint32_t sm[];
    GemmCtx c;
    c.As = sm; c.Bs = sm + 4 * PBUF;
    c.tid = threadIdx.x; c.lane = c.tid & 31; c.wid = c.tid >> 5;
    c.wm = c.wid >> 2; c.wn = c.wid & 3;
    c.g = c.lane >> 2; c.tig = c.lane & 3;

    const int z = blockIdx.z;
    const float* bias = (z == 0) ? bq : (z == 1) ? bk : bv;
    float* out = (z == 0) ? g_Q : (z == 1) ? g_K : g_V;
    const uint32_t* gwh = g_Wh + (size_t)z * Ee * (Ee / 2);
    const uint32_t* gwl = g_Wl + (size_t)z * Ee * (Ee / 2);

    const int m0 = blockIdx.x * BM;
    const int n0 = blockIdx.y * BN;

    float acc[4][4][4];
    #pragma unroll
    for (int mt = 0; mt < 4; mt++)
        #pragma unroll
        for (int nt = 0; nt < 4; nt++)
            #pragma unroll
            for (int v = 0; v < 4; v++) acc[mt][nt][v] = 0.f;

    auto load_a = [&](float4 (&avec)[4], int k0) {
        #pragma unroll
        for (int i = 0; i < 4; i++) {
            int f = c.tid + i * 256;
            int m = f >> 3, c4 = f & 7;
            avec[i] = *(const float4*)(x + (size_t)(m0 + m) * Ee + k0 + c4 * 4);
        }
    };
    auto load_b = [&](uint4 (&bhv)[2], uint4 (&blv)[2], int kt) {
        #pragma unroll
        for (int i = 0; i < 2; i++) {
            int f = c.tid + i * 256;
            int n = f >> 2, c4 = f & 3;
            size_t o = (size_t)(n0 + n) * (Ee / 2) + kt * 16 + c4 * 4;
            bhv[i] = *(const uint4*)(gwh + o);
            blv[i] = *(const uint4*)(gwl + o);
        }
    };

    constexpr int NK = Ee / BK;  // 32
    float4 avec[4]; uint4 bhv[2], blv[2];
    load_a(avec, 0); load_b(bhv, blv, 0);
    stage_a(c.As, 0, avec, c.tid);
    stage_b(c.Bs, 0, bhv, blv, c.tid);

    int buf = 0;
    for (int kt = 0; kt < NK; kt++) {
        if (kt + 1 < NK) { load_a(avec, (kt + 1) * BK); load_b(bhv, blv, kt + 1); }
        __syncthreads();
        gemm_compute_bf16(c, buf, acc);
        if (kt + 1 < NK) {
            stage_a(c.As, buf ^ 1, avec, c.tid);
            stage_b(c.Bs, buf ^ 1, bhv, blv, c.tid);
        }
        buf ^= 1;
    }

    // Epilogue: bias + scatter to [B,H,S,D]
    #pragma unroll
    for (int mt = 0; mt < 4; mt++) {
        #pragma unroll
        for (int nt = 0; nt < 4; nt++) {
            int col = n0 + c.wn * 32 + nt * 8 + c.tig * 2;
            int h = col >> 6, d = col & 63;
            float b0 = bias[h * Dd + d], b1 = bias[h * Dd + d + 1];
            int m = m0 + c.wm * 64 + mt * 16 + c.g;
            #pragma unroll
            for (int rr = 0; rr < 2; rr++) {
                int row = m + rr * 8;
                int b = row >> 11, s = row & 2047;
                float* o = out + (((size_t)(b * Hh + h)) * Ss + s) * Dd + d;
                o[0] = acc[mt][nt][rr * 2 + 0] + b0;
                o[1] = acc[mt][nt][rr * 2 + 1] + b1;
            }
        }
    }
}

// ---------------------------------------------------------------------------
// Kernel 3: output projection (2-split bf16 tensor core).
// ---------------------------------------------------------------------------
__global__ __launch_bounds__(256, 1) void out_proj_tc(float* __restrict__ out)
{
    extern __shared__ uint32_t sm[];
    GemmCtx c;
    c.As = sm; c.Bs = sm + 4 * PBUF;
    c.tid = threadIdx.x; c.lane = c.tid & 31; c.wid = c.tid >> 5;
    c.wm = c.wid >> 2; c.wn = c.wid & 3;
    c.g = c.lane >> 2; c.tig = c.lane & 3;

    const uint32_t* gwh = g_Wh + (size_t)3 * Ee * (Ee / 2);
    const uint32_t* gwl = g_Wl + (size_t)3 * Ee * (Ee / 2);
    const float* A = g_AO;

    const int m0 = blockIdx.x * BM;
    const int n0 = blockIdx.y * BN;

    float acc[4][4][4];
    #pragma unroll
    for (int mt = 0; mt < 4; mt++)
        #pragma unroll
        for (int nt = 0; nt < 4; nt++)
            #pragma unroll
            for (int v = 0; v < 4; v++) acc[mt][nt][v] = 0.f;

    auto load_a = [&](float4 (&avec)[4], int k0) {
        #pragma unroll
        for (int i = 0; i < 4; i++) {
            int f = c.tid + i * 256;
            int m = f >> 3, c4 = f & 7;
            avec[i] = *(const float4*)(A + (size_t)(m0 + m) * Ee + k0 + c4 * 4);
        }
    };
    auto load_b = [&](uint4 (&bhv)[2], uint4 (&blv)[2], int kt) {
        #pragma unroll
        for (int i = 0; i < 2; i++) {
            int f = c.tid + i * 256;
            int n = f >> 2, c4 = f & 3;
            size_t o = (size_t)(n0 + n) * (Ee / 2) + kt * 16 + c4 * 4;
            bhv[i] = *(const uint4*)(gwh + o);
            blv[i] = *(const uint4*)(gwl + o);
        }
    };

    constexpr int NK = Ee / BK;
    float4 avec[4]; uint4 bhv[2], blv[2];
    load_a(avec, 0); load_b(bhv, blv, 0);
    stage_a(c.As, 0, avec, c.tid);
    stage_b(c.Bs, 0, bhv, blv, c.tid);

    int buf = 0;
    for (int kt = 0; kt < NK; kt++) {
        if (kt + 1 < NK) { load_a(avec, (kt + 1) * BK); load_b(bhv, blv, kt + 1); }
        __syncthreads();
        gemm_compute_bf16(c, buf, acc);
        if (kt + 1 < NK) {
            stage_a(c.As, buf ^ 1, avec, c.tid);
            stage_b(c.Bs, buf ^ 1, bhv, blv, c.tid);
        }
        buf ^= 1;
    }

    #pragma unroll
    for (int mt = 0; mt < 4; mt++) {
        #pragma unroll
        for (int nt = 0; nt < 4; nt++) {
            int col = n0 + c.wn * 32 + nt * 8 + c.tig * 2;
            int m = m0 + c.wm * 64 + mt * 16 + c.g;
            #pragma unroll
            for (int rr = 0; rr < 2; rr++) {
                int row = m + rr * 8;
                out[(size_t)row * Ee + col]     = acc[mt][nt][rr * 2 + 0];
                out[(size_t)row * Ee + col + 1] = acc[mt][nt][rr * 2 + 1];
            }
        }
    }
}

// ---------------------------------------------------------------------------
// Kernel 2: causal flash attention, tf32 tensor cores (unchanged from R4).
// ---------------------------------------------------------------------------
constexpr int PSTR = 68;
constexpr int KSTR = 68;
constexpr int VSTR = 72;
constexpr int ATTN_SMEM_BYTES = (128 * PSTR + 64 * KSTR + 64 * VSTR) * 4;

__global__ __launch_bounds__(256, 1) void attn_tc()
{
    extern __shared__ uint32_t smu[];
    uint32_t* Ps = smu;                       // [128][68] (Q stage, then P)
    uint32_t* Ks = smu + 128 * PSTR;          // [64][68]
    uint32_t* Vs = Ks + 64 * KSTR;            // [64][72]

    const int qt = 15 - (int)blockIdx.x;      // heavy q-tiles first
    const int bh = blockIdx.y;
    const int q0 = qt * 128;
    const int ntiles = 2 * qt + 2;

    const float* Qg = g_Q + (size_t)bh * Ss * Dd;
    const float* Kg = g_K + (size_t)bh * Ss * Dd;
    const float* Vg = g_V + (size_t)bh * Ss * Dd;

    const int tid = threadIdx.x;
    const int lane = tid & 31;
    const int w = tid >> 5;
    const int g = lane >> 2;
    const int tig = lane & 3;
    const int w16 = w * 16;

    #pragma unroll
    for (int i = 0; i < 8; i++) {
        int f = tid + i * 256;
        int r = f >> 4, c4 = f & 15;
        float4 v = *(const float4*)(Qg + (size_t)(q0 + r) * Dd + c4 * 4);
        *(uint4*)(Ps + r * PSTR + c4 * 4) =
            make_uint4(f2tf32(v.x), f2tf32(v.y), f2tf32(v.z), f2tf32(v.w));
    }
    #pragma unroll
    for (int i = 0; i < 4; i++) {
        int f = tid + i * 256;
        int r = f >> 4, c4 = f & 15;
        float4 kv = *(const float4*)(Kg + (size_t)r * Dd + c4 * 4);
        *(uint4*)(Ks + r * KSTR + c4 * 4) =
            make_uint4(f2tf32(kv.x), f2tf32(kv.y), f2tf32(kv.z), f2tf32(kv.w));
        float4 vv = *(const float4*)(Vg + (size_t)r * Dd + c4 * 4);
        *(uint4*)(Vs + r * VSTR + c4 * 4) =
            make_uint4(f2tf32(vv.x), f2tf32(vv.y), f2tf32(vv.z), f2tf32(vv.w));
    }
    __syncthreads();

    uint32_t qf[8][4];
    #pragma unroll
    for (int kk = 0; kk < 8; kk++) {
        qf[kk][0] = Ps[(w16 + g) * PSTR + kk * 8 + tig];
        qf[kk][1] = Ps[(w16 + g + 8) * PSTR + kk * 8 + tig];
        qf[kk][2] = Ps[(w16 + g) * PSTR + kk * 8 + tig + 4];
        qf[kk][3] = Ps[(w16 + g + 8) * PSTR + kk * 8 + tig + 4];
    }

    float oacc[8][4];
    #pragma unroll
    for (int nf = 0; nf < 8; nf++)
        #pragma unroll
        for (int v = 0; v < 4; v++) oacc[nf][v] = 0.f;
    float mrow[2] = {-1e30f, -1e30f};
    float lrow[2] = {0.f, 0.f};
    const float scale = 0.125f;

    for (int t = 0; t < ntiles; t++) {
        float sacc[8][4];
        #pragma unroll
        for (int nf = 0; nf < 8; nf++)
            #pragma unroll
            for (int v = 0; v < 4; v++) sacc[nf][v] = 0.f;

        #pragma unroll
        for (int kk = 0; kk < 8; kk++) {
            #pragma unroll
            for (int nf = 0; nf < 8; nf++) {
                uint32_t b0 = Ks[(nf * 8 + g) * KSTR + kk * 8 + tig];
                uint32_t b1 = Ks[(nf * 8 + g) * KSTR + kk * 8 + tig + 4];
                mma_tf32(sacc[nf], qf[kk][0], qf[kk][1], qf[kk][2], qf[kk][3],
                         b0, b1);
            }
        }

        const int kv0 = t * 64;
        const bool domask = (t >= ntiles - 2);

        #pragma unroll
        for (int r = 0; r < 2; r++) {
            const int rowg = q0 + w16 + g + 8 * r;
            float mt = -1e30f;
            #pragma unroll
            for (int nf = 0; nf < 8; nf++) {
                float s0 = sacc[nf][2 * r]     * scale;
                float s1 = sacc[nf][2 * r + 1] * scale;
                if (domask) {
                    int col = kv0 + nf * 8 + 2 * tig;
                    if (col > rowg)     s0 = -1e30f;
                    if (col + 1 > rowg) s1 = -1e30f;
                }
                sacc[nf][2 * r] = s0; sacc[nf][2 * r + 1] = s1;
                mt = fmaxf(mt, fmaxf(s0, s1));
            }
            mt = fmaxf(mt, __shfl_xor_sync(0xffffffffu, mt, 1, 4));
            mt = fmaxf(mt, __shfl_xor_sync(0xffffffffu, mt, 2, 4));
            float mnew = fmaxf(mrow[r], mt);
            float corr = __expf(mrow[r] - mnew);
            float rs = 0.f;
            #pragma unroll
            for (int nf = 0; nf < 8; nf++) {
                float p0 = __expf(sacc[nf][2 * r] - mnew);
                float p1 = __expf(sacc[nf][2 * r + 1] - mnew);
                rs += p0 + p1;
                uint32_t* pp = Ps + (w16 + g + 8 * r) * PSTR + nf * 8 + 2 * tig;
                pp[0] = f2tf32(p0); pp[1] = f2tf32(p1);
            }
            rs += __shfl_xor_sync(0xffffffffu, rs, 1, 4);
            rs += __shfl_xor_sync(0xffffffffu, rs, 2, 4);
            lrow[r] = lrow[r] * corr + rs;
            mrow[r] = mnew;
            #pragma unroll
            for (int nf = 0; nf < 8; nf++) {
                oacc[nf][2 * r]     *= corr;
                oacc[nf][2 * r + 1] *= corr;
            }
        }
        __syncwarp();

        #pragma unroll
        for (int kk = 0; kk < 8; kk++) {
            uint32_t a0 = Ps[(w16 + g) * PSTR + kk * 8 + tig];
            uint32_t a1 = Ps[(w16 + g + 8) * PSTR + kk * 8 + tig];
            uint32_t a2 = Ps[(w16 + g) * PSTR + kk * 8 + tig + 4];
            uint32_t a3 = Ps[(w16 + g + 8) * PSTR + kk * 8 + tig + 4];
            #pragma unroll
            for (int nf = 0; nf < 8; nf++) {
                uint32_t b0 = Vs[(kk * 8 + tig) * VSTR + nf * 8 + g];
                uint32_t b1 = Vs[(kk * 8 + tig + 4) * VSTR + nf * 8 + g];
                mma_tf32(oacc[nf], a0, a1, a2, a3, b0, b1);
            }
        }

        if (t + 1 < ntiles) {
            __syncthreads();
            const int k0n = (t + 1) * 64;
            #pragma unroll
            for (int i = 0; i < 4; i++) {
                int f = tid + i * 256;
                int r2 = f >> 4, c4 = f & 15;
                float4 kv = *(const float4*)(Kg + (size_t)(k0n + r2) * Dd + c4 * 4);
                *(uint4*)(Ks + r2 * KSTR + c4 * 4) =
                    make_uint4(f2tf32(kv.x), f2tf32(kv.y), f2tf32(kv.z), f2tf32(kv.w));
                float4 vv = *(const float4*)(Vg + (size_t)(k0n + r2) * Dd + c4 * 4);
                *(uint4*)(Vs + r2 * VSTR + c4 * 4) =
                    make_uint4(f2tf32(vv.x), f2tf32(vv.y), f2tf32(vv.z), f2tf32(vv.w));
            }
            __syncthreads();
        }
    }

    const int b = bh >> 4, h = bh & 15;
    float* dst = g_AO + (size_t)b * Ss * Ee + h * Dd;
    #pragma unroll
    for (int r = 0; r < 2; r++) {
        float inv = 1.0f / lrow[r];
        int s = q0 + w16 + g + 8 * r;
        #pragma unroll
        for (int nf = 0; nf < 8; nf++) {
            int d = nf * 8 + 2 * tig;
            dst[(size_t)s * Ee + d]     = oacc[nf][2 * r]     * inv;
            dst[(size_t)s * Ee + d + 1] = oacc[nf][2 * r + 1] * inv;
        }
    }
}

// ---------------------------------------------------------------------------
// Launch
// ---------------------------------------------------------------------------
extern "C" void kernel_launch(void* const* d_in, const int* in_sizes, int n_in,
                              void* d_out, int out_size)
{
    const float* x  = (const float*)d_in[0];
    const float* Wq = (const float*)d_in[1];
    const float* bq = (const float*)d_in[2];
    const float* Wk = (const float*)d_in[3];
    const float* bk = (const float*)d_in[4];
    const float* Wv = (const float*)d_in[5];
    const float* bv = (const float*)d_in[6];
    const float* Wo = (const float*)d_in[7];
    float* out = (float*)d_out;

    static bool attr_set = false;
    if (!attr_set) {
        cudaFuncSetAttribute(proj_qkv_tc,
            cudaFuncAttributeMaxDynamicSharedMemorySize, GEMM_SMEM_BYTES);
        cudaFuncSetAttribute(out_proj_tc,
            cudaFuncAttributeMaxDynamicSharedMemorySize, GEMM_SMEM_BYTES);
        cudaFuncSetAttribute(attn_tc,
            cudaFuncAttributeMaxDynamicSharedMemorySize, ATTN_SMEM_BYTES);
        attr_set = true;
    }

    // Pre-pack weights: transpose + bf16 hi/lo split
    prep_pack<<<dim3(32, 32, 4), 256>>>(Wq, Wk, Wv, Wo);

    // QKV projections: 4096/128 x 1024/128 x {Q,K,V}
    proj_qkv_tc<<<dim3(32, 8, 3), 256, GEMM_SMEM_BYTES>>>(x, bq, bk, bv);

    // Flash attention: 16 q-tiles x 32 (b,h)
    attn_tc<<<dim3(16, Bb * Hh), 256, ATTN_SMEM_BYTES>>>();

    // Output projection
    out_proj_tc<<<dim3(32, 8), 256, GEMM_SMEM_BYTES>>>(out);
}

// round 7
// speedup vs baseline: 3.1139x; 1.0653x over previous
#include <cuda_runtime.h>
#include <cuda_bf16.h>
#include <math.h>
#include <stdint.h>

// Problem constants
constexpr int Bb = 2;
constexpr int Ss = 2048;
constexpr int Ee = 1024;
constexpr int Hh = 16;
constexpr int Dd = 64;
constexpr int KP = Ee / 2;   // packed u32 (bf16x2) per row

// Scratch (device globals — no allocation allowed)
// g_Q/g_K/g_V hold values already RNA-rounded to tf32 precision.
__device__ float g_Q[(size_t)Bb * Hh * Ss * Dd];   // [B,H,S,D]
__device__ float g_K[(size_t)Bb * Hh * Ss * Dd];
__device__ float g_V[(size_t)Bb * Hh * Ss * Dd];
// Pre-packed bf16 hi/lo operands (u32 = 2 bf16, k-pairs minor)
__device__ uint32_t g_Wh[(size_t)4 * Ee * KP];     // weights, [z][n][kp]
__device__ uint32_t g_Wl[(size_t)4 * Ee * KP];
__device__ uint32_t g_Xh[(size_t)Bb * Ss * KP];    // x, [row][kp]
__device__ uint32_t g_Xl[(size_t)Bb * Ss * KP];
__device__ uint32_t g_AOh[(size_t)Bb * Ss * KP];   // attn out, [row][kp]
__device__ uint32_t g_AOl[(size_t)Bb * Ss * KP];

// ---------------------------------------------------------------------------
// Helpers
// ---------------------------------------------------------------------------
__device__ __forceinline__ uint32_t f2tf32(float f) {
    uint32_t u;
    asm("cvt.rna.tf32.f32 %0, %1;" : "=r"(u) : "f"(f));
    return u;
}

__device__ __forceinline__ uint32_t pack_bf16x2(float e_even, float e_odd) {
    uint32_t r;
    asm("cvt.rn.bf16x2.f32 %0, %1, %2;" : "=r"(r) : "f"(e_odd), "f"(e_even));
    return r;
}

__device__ __forceinline__ void split2(float v0, float v1,
                                       uint32_t& hi, uint32_t& lo) {
    float h0 = __bfloat162float(__float2bfloat16(v0));
    float h1 = __bfloat162float(__float2bfloat16(v1));
    hi = pack_bf16x2(h0, h1);
    lo = pack_bf16x2(v0 - h0, v1 - h1);
}

__device__ __forceinline__ void mma_tf32(float c[4], uint32_t a0, uint32_t a1,
                                         uint32_t a2, uint32_t a3,
                                         uint32_t b0, uint32_t b1) {
    asm volatile(
        "mma.sync.aligned.m16n8k8.row.col.f32.tf32.tf32.f32 "
        "{%0,%1,%2,%3}, {%4,%5,%6,%7}, {%8,%9}, {%0,%1,%2,%3};\n"
        : "+f"(c[0]), "+f"(c[1]), "+f"(c[2]), "+f"(c[3])
        : "r"(a0), "r"(a1), "r"(a2), "r"(a3), "r"(b0), "r"(b1));
}

__device__ __forceinline__ void mma_bf16(float c[4], uint32_t a0, uint32_t a1,
                                         uint32_t a2, uint32_t a3,
                                         uint32_t b0, uint32_t b1) {
    asm volatile(
        "mma.sync.aligned.m16n8k16.row.col.f32.bf16.bf16.f32 "
        "{%0,%1,%2,%3}, {%4,%5,%6,%7}, {%8,%9}, {%0,%1,%2,%3};\n"
        : "+f"(c[0]), "+f"(c[1]), "+f"(c[2]), "+f"(c[3])
        : "r"(a0), "r"(a1), "r"(a2), "r"(a3), "r"(b0), "r"(b1));
}

__device__ __forceinline__ void cp16(uint32_t dst_smem, const void* src) {
    asm volatile("cp.async.cg.shared.global [%0], [%1], 16;"
                 :: "r"(dst_smem), "l"(src));
}
__device__ __forceinline__ void cp_commit() {
    asm volatile("cp.async.commit_group;");
}
template <int N>
__device__ __forceinline__ void cp_wait() {
    asm volatile("cp.async.wait_group %0;" :: "n"(N));
}

// ---------------------------------------------------------------------------
// Kernel 0a: weight pre-pack. Transpose W to [n][kpair], split bf16 hi/lo.
// ---------------------------------------------------------------------------
__global__ __launch_bounds__(256) void prep_pack(
    const float* __restrict__ Wq, const float* __restrict__ Wk,
    const float* __restrict__ Wv, const float* __restrict__ Wo)
{
    __shared__ float t[32][33];
    const int k0 = blockIdx.x * 32, n0 = blockIdx.y * 32;
    const int z = blockIdx.z;
    const float* W = (z == 0) ? Wq : (z == 1) ? Wk : (z == 2) ? Wv : Wo;
    const int tid = threadIdx.x;

    #pragma unroll
    for (int it = 0; it < 4; it++) {
        int idx = tid + it * 256;
        int kk = idx >> 5, nn = idx & 31;
        float v;
        if (z < 3) {
            int n = n0 + nn, h = n >> 6, d = n & 63;
            v = W[((size_t)h * Ee + (k0 + kk)) * Dd + d];
        } else {
            v = W[(size_t)(k0 + kk) * Ee + (n0 + nn)];
        }
        t[kk][nn] = v;
    }
    __syncthreads();

    uint32_t* hi = g_Wh + (size_t)z * Ee * KP;
    uint32_t* lo = g_Wl + (size_t)z * Ee * KP;
    #pragma unroll
    for (int it = 0; it < 2; it++) {
        int idx = tid + it * 256;
        int nn = idx >> 4, kp = idx & 15;
        uint32_t h, l;
        split2(t[2 * kp][nn], t[2 * kp + 1][nn], h, l);
        size_t o = (size_t)(n0 + nn) * KP + (k0 >> 1) + kp;
        hi[o] = h; lo[o] = l;
    }
}

// ---------------------------------------------------------------------------
// Kernel 0b: x pre-pack (no transpose, row-major kp-minor).
// ---------------------------------------------------------------------------
__global__ __launch_bounds__(256) void pack_x(const float* __restrict__ x)
{
    int idx = blockIdx.x * 256 + threadIdx.x;
    float4 v = ((const float4*)x)[idx];
    uint32_t h0, l0, h1, l1;
    split2(v.x, v.y, h0, l0);
    split2(v.z, v.w, h1, l1);
    ((uint2*)g_Xh)[idx] = make_uint2(h0, h1);
    ((uint2*)g_Xl)[idx] = make_uint2(l0, l1);
}

// ---------------------------------------------------------------------------
// 2-split bf16 GEMM, CTA 128x128x32, 8 warps, cp.async 2-stage pipeline,
// 2 CTAs/SM. acc += Ah*Bh + Ah*Bl + Al*Bh.
// ---------------------------------------------------------------------------
constexpr int BM = 128, BN = 128, BK = 32;
constexpr int PSTRIDE = 20;
constexpr int PBUF = 128 * PSTRIDE;               // 2560 u32
constexpr int GEMM_SMEM_BYTES = 8 * PBUF * 4;     // 81920 B
constexpr int NKT = Ee / BK;                      // 32

struct GemmCtx {
    uint32_t* As;
    uint32_t* Bs;
    int tid, lane, wid, wm, wn, g, tig;
};

__device__ __forceinline__ void gemm_compute_bf16(const GemmCtx& c, int buf,
                                                  float acc[4][4][4]) {
    const uint32_t* Ah = c.As + buf * PBUF;
    const uint32_t* Al = Ah + 2 * PBUF;
    const uint32_t* Bh = c.Bs + buf * PBUF;
    const uint32_t* Bl = Bh + 2 * PBUF;
    #pragma unroll
    for (int s = 0; s < 2; s++) {
        const int cb = 8 * s;
        uint32_t bh_[4][2], bl_[4][2];
        #pragma unroll
        for (int nt = 0; nt < 4; nt++) {
            int n = c.wn * 32 + nt * 8 + c.g;
            bh_[nt][0] = Bh[n * PSTRIDE + cb + c.tig];
            bh_[nt][1] = Bh[n * PSTRIDE + cb + c.tig + 4];
            bl_[nt][0] = Bl[n * PSTRIDE + cb + c.tig];
            bl_[nt][1] = Bl[n * PSTRIDE + cb + c.tig + 4];
        }
        #pragma unroll
        for (int mt = 0; mt < 4; mt++) {
            int r0 = c.wm * 64 + mt * 16 + c.g, r1 = r0 + 8;
            uint32_t ah0 = Ah[r0 * PSTRIDE + cb + c.tig];
            uint32_t ah1 = Ah[r1 * PSTRIDE + cb + c.tig];
            uint32_t ah2 = Ah[r0 * PSTRIDE + cb + c.tig + 4];
            uint32_t ah3 = Ah[r1 * PSTRIDE + cb + c.tig + 4];
            uint32_t al0 = Al[r0 * PSTRIDE + cb + c.tig];
            uint32_t al1 = Al[r1 * PSTRIDE + cb + c.tig];
            uint32_t al2 = Al[r0 * PSTRIDE + cb + c.tig + 4];
            uint32_t al3 = Al[r1 * PSTRIDE + cb + c.tig + 4];
            #pragma unroll
            for (int nt = 0; nt < 4; nt++) {
                mma_bf16(acc[mt][nt], ah0, ah1, ah2, ah3, bh_[nt][0], bh_[nt][1]);
                mma_bf16(acc[mt][nt], ah0, ah1, ah2, ah3, bl_[nt][0], bl_[nt][1]);
                mma_bf16(acc[mt][nt], al0, al1, al2, al3, bh_[nt][0], bh_[nt][1]);
            }
        }
    }
}

__device__ __forceinline__ void gemm_issue(
    uint32_t sA, uint32_t sB, int buf, int kt, int tid, int m0, int n0,
    const uint32_t* gAh, const uint32_t* gAl,
    const uint32_t* gBh, const uint32_t* gBl)
{
    #pragma unroll
    for (int i = 0; i < 2; i++) {
        int f = tid + i * 256;
        int row = f >> 2, c4 = f & 3;
        uint32_t dA = sA + (buf * PBUF + row * PSTRIDE + c4 * 4) * 4;
        size_t oa = (size_t)(m0 + row) * KP + kt * 16 + c4 * 4;
        cp16(dA, gAh + oa);
        cp16(dA + 2 * PBUF * 4, gAl + oa);
        uint32_t dB = sB + (buf * PBUF + row * PSTRIDE + c4 * 4) * 4;
        size_t ob = (size_t)(n0 + row) * KP + kt * 16 + c4 * 4;
        cp16(dB, gBh + ob);
        cp16(dB + 2 * PBUF * 4, gBl + ob);
    }
    cp_commit();
}

// ---------------------------------------------------------------------------
// Kernel 1: fused QKV projection. Output RNA-rounded to tf32 precision so
// attention can consume raw bits with R5-identical numerics.
// ---------------------------------------------------------------------------
__global__ __launch_bounds__(256, 2) void proj_qkv_tc(
    const float* __restrict__ bq, const float* __restrict__ bk,
    const float* __restrict__ bv)
{
    extern __shared__ uint32_t sm[];
    GemmCtx c;
    c.As = sm; c.Bs = sm + 4 * PBUF;
    c.tid = threadIdx.x; c.lane = c.tid & 31; c.wid = c.tid >> 5;
    c.wm = c.wid >> 2; c.wn = c.wid & 3;
    c.g = c.lane >> 2; c.tig = c.lane & 3;

    const int z = blockIdx.z;
    const float* bias = (z == 0) ? bq : (z == 1) ? bk : bv;
    float* out = (z == 0) ? g_Q : (z == 1) ? g_K : g_V;
    const uint32_t* gBh = g_Wh + (size_t)z * Ee * KP;
    const uint32_t* gBl = g_Wl + (size_t)z * Ee * KP;

    const int m0 = blockIdx.x * BM;
    const int n0 = blockIdx.y * BN;

    uint32_t sA = (uint32_t)__cvta_generic_to_shared(sm);
    uint32_t sB = sA + 4 * PBUF * 4;

    float acc[4][4][4];
    #pragma unroll
    for (int mt = 0; mt < 4; mt++)
        #pragma unroll
        for (int nt = 0; nt < 4; nt++)
            #pragma unroll
            for (int v = 0; v < 4; v++) acc[mt][nt][v] = 0.f;

    gemm_issue(sA, sB, 0, 0, c.tid, m0, n0, g_Xh, g_Xl, gBh, gBl);
    gemm_issue(sA, sB, 1, 1, c.tid, m0, n0, g_Xh, g_Xl, gBh, gBl);

    int buf = 0;
    for (int kt = 0; kt < NKT; kt++) {
        if (kt + 1 < NKT) cp_wait<1>(); else cp_wait<0>();
        __syncthreads();
        gemm_compute_bf16(c, buf, acc);
        __syncthreads();
        if (kt + 2 < NKT)
            gemm_issue(sA, sB, buf, kt + 2, c.tid, m0, n0, g_Xh, g_Xl, gBh, gBl);
        buf ^= 1;
    }

    // Epilogue: bias + RNA-round to tf32 + scatter to [B,H,S,D]
    #pragma unroll
    for (int mt = 0; mt < 4; mt++) {
        #pragma unroll
        for (int nt = 0; nt < 4; nt++) {
            int col = n0 + c.wn * 32 + nt * 8 + c.tig * 2;
            int h = col >> 6, d = col & 63;
            float b0 = bias[h * Dd + d], b1 = bias[h * Dd + d + 1];
            int m = m0 + c.wm * 64 + mt * 16 + c.g;
            #pragma unroll
            for (int rr = 0; rr < 2; rr++) {
                int row = m + rr * 8;
                int b = row >> 11, s = row & 2047;
                float* o = out + (((size_t)(b * Hh + h)) * Ss + s) * Dd + d;
                o[0] = __uint_as_float(f2tf32(acc[mt][nt][rr * 2 + 0] + b0));
                o[1] = __uint_as_float(f2tf32(acc[mt][nt][rr * 2 + 1] + b1));
            }
        }
    }
}

// ---------------------------------------------------------------------------
// Kernel 3: output projection (reads packed attn output).
// ---------------------------------------------------------------------------
__global__ __launch_bounds__(256, 2) void out_proj_tc(float* __restrict__ out)
{
    extern __shared__ uint32_t sm[];
    GemmCtx c;
    c.As = sm; c.Bs = sm + 4 * PBUF;
    c.tid = threadIdx.x; c.lane = c.tid & 31; c.wid = c.tid >> 5;
    c.wm = c.wid >> 2; c.wn = c.wid & 3;
    c.g = c.lane >> 2; c.tig = c.lane & 3;

    const uint32_t* gBh = g_Wh + (size_t)3 * Ee * KP;
    const uint32_t* gBl = g_Wl + (size_t)3 * Ee * KP;

    const int m0 = blockIdx.x * BM;
    const int n0 = blockIdx.y * BN;

    uint32_t sA = (uint32_t)__cvta_generic_to_shared(sm);
    uint32_t sB = sA + 4 * PBUF * 4;

    float acc[4][4][4];
    #pragma unroll
    for (int mt = 0; mt < 4; mt++)
        #pragma unroll
        for (int nt = 0; nt < 4; nt++)
            #pragma unroll
            for (int v = 0; v < 4; v++) acc[mt][nt][v] = 0.f;

    gemm_issue(sA, sB, 0, 0, c.tid, m0, n0, g_AOh, g_AOl, gBh, gBl);
    gemm_issue(sA, sB, 1, 1, c.tid, m0, n0, g_AOh, g_AOl, gBh, gBl);

    int buf = 0;
    for (int kt = 0; kt < NKT; kt++) {
        if (kt + 1 < NKT) cp_wait<1>(); else cp_wait<0>();
        __syncthreads();
        gemm_compute_bf16(c, buf, acc);
        __syncthreads();
        if (kt + 2 < NKT)
            gemm_issue(sA, sB, buf, kt + 2, c.tid, m0, n0, g_AOh, g_AOl, gBh, gBl);
        buf ^= 1;
    }

    #pragma unroll
    for (int mt = 0; mt < 4; mt++) {
        #pragma unroll
        for (int nt = 0; nt < 4; nt++) {
            int col = n0 + c.wn * 32 + nt * 8 + c.tig * 2;
            int m = m0 + c.wm * 64 + mt * 16 + c.g;
            #pragma unroll
            for (int rr = 0; rr < 2; rr++) {
                int row = m + rr * 8;
                out[(size_t)row * Ee + col]     = acc[mt][nt][rr * 2 + 0];
                out[(size_t)row * Ee + col + 1] = acc[mt][nt][rr * 2 + 1];
            }
        }
    }
}

// ---------------------------------------------------------------------------
// Kernel 2: causal flash attention. Inputs in global are already tf32-RNA
// rounded, so cp.async raw loads give R5-identical numerics. P is RNA-rounded
// before the smem store.
// ---------------------------------------------------------------------------
constexpr int PSTR = 68;
constexpr int KSTR = 68;
constexpr int VSTR = 72;
constexpr int ATTN_SMEM_BYTES =
    (128 * PSTR + 2 * 64 * KSTR + 2 * 64 * VSTR) * 4;  // 106496 B

__global__ __launch_bounds__(256, 1) void attn_tc()
{
    extern __shared__ uint32_t smu[];
    uint32_t* Ps = smu;                             // [128][68]
    uint32_t* Ks = smu + 128 * PSTR;                // [2][64][68]
    uint32_t* Vs = Ks + 2 * 64 * KSTR;              // [2][64][72]

    const int qt = 15 - (int)blockIdx.x;
    const int bh = blockIdx.y;
    const int q0 = qt * 128;
    const int ntiles = 2 * qt + 2;

    const float* Qg = g_Q + (size_t)bh * Ss * Dd;
    const float* Kg = g_K + (size_t)bh * Ss * Dd;
    const float* Vg = g_V + (size_t)bh * Ss * Dd;

    const int tid = threadIdx.x;
    const int lane = tid & 31;
    const int w = tid >> 5;
    const int g = lane >> 2;
    const int tig = lane & 3;
    const int w16 = w * 16;

    const uint32_t sKbase = (uint32_t)__cvta_generic_to_shared(Ks);
    const uint32_t sVbase = (uint32_t)__cvta_generic_to_shared(Vs);

    auto issue_kv = [&](int t, int b) {
        const int k0 = t * 64;
        #pragma unroll
        for (int i = 0; i < 4; i++) {
            int f = tid + i * 256;
            int r = f >> 4, c4 = f & 15;
            cp16(sKbase + (b * 64 * KSTR + r * KSTR + c4 * 4) * 4,
                 Kg + (size_t)(k0 + r) * Dd + c4 * 4);
            cp16(sVbase + (b * 64 * VSTR + r * VSTR + c4 * 4) * 4,
                 Vg + (size_t)(k0 + r) * Dd + c4 * 4);
        }
        cp_commit();
    };

    issue_kv(0, 0);
    if (ntiles > 1) issue_kv(1, 1);

    // Stage Q tile (already tf32-rounded in global)
    #pragma unroll
    for (int i = 0; i < 8; i++) {
        int f = tid + i * 256;
        int r = f >> 4, c4 = f & 15;
        float4 v = *(const float4*)(Qg + (size_t)(q0 + r) * Dd + c4 * 4);
        *(uint4*)(Ps + r * PSTR + c4 * 4) =
            make_uint4(__float_as_uint(v.x), __float_as_uint(v.y),
                       __float_as_uint(v.z), __float_as_uint(v.w));
    }
    __syncthreads();

    uint32_t qf[8][4];
    #pragma unroll
    for (int kk = 0; kk < 8; kk++) {
        qf[kk][0] = Ps[(w16 + g) * PSTR + kk * 8 + tig];
        qf[kk][1] = Ps[(w16 + g + 8) * PSTR + kk * 8 + tig];
        qf[kk][2] = Ps[(w16 + g) * PSTR + kk * 8 + tig + 4];
        qf[kk][3] = Ps[(w16 + g + 8) * PSTR + kk * 8 + tig + 4];
    }

    float oacc[8][4];
    #pragma unroll
    for (int nf = 0; nf < 8; nf++)
        #pragma unroll
        for (int v = 0; v < 4; v++) oacc[nf][v] = 0.f;
    float mrow[2] = {-1e30f, -1e30f};
    float lrow[2] = {0.f, 0.f};
    const float scale = 0.125f;

    int buf = 0;
    for (int t = 0; t < ntiles; t++) {
        if (t + 1 < ntiles) cp_wait<1>(); else cp_wait<0>();
        __syncthreads();

        const uint32_t* Kb = Ks + buf * 64 * KSTR;
        const uint32_t* Vb = Vs + buf * 64 * VSTR;

        float sacc[8][4];
        #pragma unroll
        for (int nf = 0; nf < 8; nf++)
            #pragma unroll
            for (int v = 0; v < 4; v++) sacc[nf][v] = 0.f;

        #pragma unroll
        for (int kk = 0; kk < 8; kk++) {
            #pragma unroll
            for (int nf = 0; nf < 8; nf++) {
                uint32_t b0 = Kb[(nf * 8 + g) * KSTR + kk * 8 + tig];
                uint32_t b1 = Kb[(nf * 8 + g) * KSTR + kk * 8 + tig + 4];
                mma_tf32(sacc[nf], qf[kk][0], qf[kk][1], qf[kk][2], qf[kk][3],
                         b0, b1);
            }
        }

        const int kv0 = t * 64;
        const bool domask = (t >= ntiles - 2);

        #pragma unroll
        for (int r = 0; r < 2; r++) {
            const int rowg = q0 + w16 + g + 8 * r;
            float mt = -1e30f;
            #pragma unroll
            for (int nf = 0; nf < 8; nf++) {
                float s0 = sacc[nf][2 * r]     * scale;
                float s1 = sacc[nf][2 * r + 1] * scale;
                if (domask) {
                    int col = kv0 + nf * 8 + 2 * tig;
                    if (col > rowg)     s0 = -1e30f;
                    if (col + 1 > rowg) s1 = -1e30f;
                }
                sacc[nf][2 * r] = s0; sacc[nf][2 * r + 1] = s1;
                mt = fmaxf(mt, fmaxf(s0, s1));
            }
            mt = fmaxf(mt, __shfl_xor_sync(0xffffffffu, mt, 1, 4));
            mt = fmaxf(mt, __shfl_xor_sync(0xffffffffu, mt, 2, 4));
            float mnew = fmaxf(mrow[r], mt);
            float corr = __expf(mrow[r] - mnew);
            float rs = 0.f;
            #pragma unroll
            for (int nf = 0; nf < 8; nf++) {
                float p0 = __expf(sacc[nf][2 * r] - mnew);
                float p1 = __expf(sacc[nf][2 * r + 1] - mnew);
                rs += p0 + p1;
                uint32_t* pp = Ps + (w16 + g + 8 * r) * PSTR + nf * 8 + 2 * tig;
                pp[0] = f2tf32(p0); pp[1] = f2tf32(p1);
            }
            rs += __shfl_xor_sync(0xffffffffu, rs, 1, 4);
            rs += __shfl_xor_sync(0xffffffffu, rs, 2, 4);
            lrow[r] = lrow[r] * corr + rs;
            mrow[r] = mnew;
            #pragma unroll
            for (int nf = 0; nf < 8; nf++) {
                oacc[nf][2 * r]     *= corr;
                oacc[nf][2 * r + 1] *= corr;
            }
        }
        __syncwarp();

        #pragma unroll
        for (int kk = 0; kk < 8; kk++) {
            uint32_t a0 = Ps[(w16 + g) * PSTR + kk * 8 + tig];
            uint32_t a1 = Ps[(w16 + g + 8) * PSTR + kk * 8 + tig];
            uint32_t a2 = Ps[(w16 + g) * PSTR + kk * 8 + tig + 4];
            uint32_t a3 = Ps[(w16 + g + 8) * PSTR + kk * 8 + tig + 4];
            #pragma unroll
            for (int nf = 0; nf < 8; nf++) {
                uint32_t b0 = Vb[(kk * 8 + tig) * VSTR + nf * 8 + g];
                uint32_t b1 = Vb[(kk * 8 + tig + 4) * VSTR + nf * 8 + g];
                mma_tf32(oacc[nf], a0, a1, a2, a3, b0, b1);
            }
        }

        __syncthreads();
        if (t + 2 < ntiles) issue_kv(t + 2, buf);
        buf ^= 1;
    }

    // Epilogue: normalize + write PACKED bf16 hi/lo [B*S][kp]
    const int b = bh >> 4, h = bh & 15;
    #pragma unroll
    for (int r = 0; r < 2; r++) {
        float inv = 1.0f / lrow[r];
        int s = q0 + w16 + g + 8 * r;
        size_t rowbase = (size_t)(b * Ss + s) * KP;
        #pragma unroll
        for (int nf = 0; nf < 8; nf++) {
            int d = nf * 8 + 2 * tig;
            float o0 = oacc[nf][2 * r] * inv;
            float o1 = oacc[nf][2 * r + 1] * inv;
            uint32_t hi, lo;
            split2(o0, o1, hi, lo);
            size_t off = rowbase + ((h * Dd + d) >> 1);
            g_AOh[off] = hi;
            g_AOl[off] = lo;
        }
    }
}

// ---------------------------------------------------------------------------
// Launch
// ---------------------------------------------------------------------------
extern "C" void kernel_launch(void* const* d_in, const int* in_sizes, int n_in,
                              void* d_out, int out_size)
{
    const float* x  = (const float*)d_in[0];
    const float* Wq = (const float*)d_in[1];
    const float* bq = (const float*)d_in[2];
    const float* Wk = (const float*)d_in[3];
    const float* bk = (const float*)d_in[4];
    const float* Wv = (const float*)d_in[5];
    const float* bv = (const float*)d_in[6];
    const float* Wo = (const float*)d_in[7];
    float* out = (float*)d_out;

    static bool attr_set = false;
    if (!attr_set) {
        cudaFuncSetAttribute(proj_qkv_tc,
            cudaFuncAttributeMaxDynamicSharedMemorySize, GEMM_SMEM_BYTES);
        cudaFuncSetAttribute(out_proj_tc,
            cudaFuncAttributeMaxDynamicSharedMemorySize, GEMM_SMEM_BYTES);
        cudaFuncSetAttribute(attn_tc,
            cudaFuncAttributeMaxDynamicSharedMemorySize, ATTN_SMEM_BYTES);
        attr_set = true;
    }

    // Pre-pack weights and x
    prep_pack<<<dim3(32, 32, 4), 256>>>(Wq, Wk, Wv, Wo);
    pack_x<<<dim3(Bb * Ss * Ee / 4 / 256), 256>>>(x);

    // QKV projections
    proj_qkv_tc<<<dim3(32, 8, 3), 256, GEMM_SMEM_BYTES>>>(bq, bk, bv);

    // Flash attention
    attn_tc<<<dim3(16, Bb * Hh), 256, ATTN_SMEM_BYTES>>>();

    // Output projection
    out_proj_tc<<<dim3(32, 8), 256, GEMM_SMEM_BYTES>>>(out);
}

// round 8
// speedup vs baseline: 3.3753x; 1.0839x over previous
#include <cuda_runtime.h>
#include <cuda_bf16.h>
#include <math.h>
#include <stdint.h>

// Problem constants
constexpr int Bb = 2;
constexpr int Ss = 2048;
constexpr int Ee = 1024;
constexpr int Hh = 16;
constexpr int Dd = 64;
constexpr int KP = Ee / 2;   // packed u32 (bf16x2) per row

// Scratch (device globals — no allocation allowed)
// g_Q/g_K/g_V hold values already RNA-rounded to tf32 precision.
__device__ float g_Q[(size_t)Bb * Hh * Ss * Dd];   // [B,H,S,D]
__device__ float g_K[(size_t)Bb * Hh * Ss * Dd];
__device__ float g_V[(size_t)Bb * Hh * Ss * Dd];
// Pre-packed bf16 hi/lo operands (u32 = 2 bf16, k-pairs minor)
__device__ uint32_t g_Wh[(size_t)4 * Ee * KP];     // weights, [z][n][kp]
__device__ uint32_t g_Wl[(size_t)4 * Ee * KP];
__device__ uint32_t g_Xh[(size_t)Bb * Ss * KP];    // x, [row][kp]
__device__ uint32_t g_Xl[(size_t)Bb * Ss * KP];
__device__ uint32_t g_AOh[(size_t)Bb * Ss * KP];   // attn out, [row][kp]
__device__ uint32_t g_AOl[(size_t)Bb * Ss * KP];

// ---------------------------------------------------------------------------
// Helpers
// ---------------------------------------------------------------------------
__device__ __forceinline__ uint32_t f2tf32(float f) {
    uint32_t u;
    asm("cvt.rna.tf32.f32 %0, %1;" : "=r"(u) : "f"(f));
    return u;
}

__device__ __forceinline__ uint32_t pack_bf16x2(float e_even, float e_odd) {
    uint32_t r;
    asm("cvt.rn.bf16x2.f32 %0, %1, %2;" : "=r"(r) : "f"(e_odd), "f"(e_even));
    return r;
}

__device__ __forceinline__ void split2(float v0, float v1,
                                       uint32_t& hi, uint32_t& lo) {
    float h0 = __bfloat162float(__float2bfloat16(v0));
    float h1 = __bfloat162float(__float2bfloat16(v1));
    hi = pack_bf16x2(h0, h1);
    lo = pack_bf16x2(v0 - h0, v1 - h1);
}

__device__ __forceinline__ void mma_tf32(float c[4], uint32_t a0, uint32_t a1,
                                         uint32_t a2, uint32_t a3,
                                         uint32_t b0, uint32_t b1) {
    asm volatile(
        "mma.sync.aligned.m16n8k8.row.col.f32.tf32.tf32.f32 "
        "{%0,%1,%2,%3}, {%4,%5,%6,%7}, {%8,%9}, {%0,%1,%2,%3};\n"
        : "+f"(c[0]), "+f"(c[1]), "+f"(c[2]), "+f"(c[3])
        : "r"(a0), "r"(a1), "r"(a2), "r"(a3), "r"(b0), "r"(b1));
}

__device__ __forceinline__ void mma_bf16(float c[4], uint32_t a0, uint32_t a1,
                                         uint32_t a2, uint32_t a3,
                                         uint32_t b0, uint32_t b1) {
    asm volatile(
        "mma.sync.aligned.m16n8k16.row.col.f32.bf16.bf16.f32 "
        "{%0,%1,%2,%3}, {%4,%5,%6,%7}, {%8,%9}, {%0,%1,%2,%3};\n"
        : "+f"(c[0]), "+f"(c[1]), "+f"(c[2]), "+f"(c[3])
        : "r"(a0), "r"(a1), "r"(a2), "r"(a3), "r"(b0), "r"(b1));
}

// ldmatrix x4: each lane supplies one 16B row address; 4 8x8(b16) matrices.
__device__ __forceinline__ void ldsm_x4(uint32_t& r0, uint32_t& r1,
                                        uint32_t& r2, uint32_t& r3,
                                        uint32_t saddr) {
    asm volatile(
        "ldmatrix.sync.aligned.m8n8.x4.shared.b16 {%0,%1,%2,%3}, [%4];"
        : "=r"(r0), "=r"(r1), "=r"(r2), "=r"(r3) : "r"(saddr));
}

__device__ __forceinline__ void cp16(uint32_t dst_smem, const void* src) {
    asm volatile("cp.async.cg.shared.global [%0], [%1], 16;"
                 :: "r"(dst_smem), "l"(src));
}
__device__ __forceinline__ void cp_commit() {
    asm volatile("cp.async.commit_group;");
}
template <int N>
__device__ __forceinline__ void cp_wait() {
    asm volatile("cp.async.wait_group %0;" :: "n"(N));
}

// ---------------------------------------------------------------------------
// Kernel 0a: weight pre-pack. Transpose W to [n][kpair], split bf16 hi/lo.
// ---------------------------------------------------------------------------
__global__ __launch_bounds__(256) void prep_pack(
    const float* __restrict__ Wq, const float* __restrict__ Wk,
    const float* __restrict__ Wv, const float* __restrict__ Wo)
{
    __shared__ float t[32][33];
    const int k0 = blockIdx.x * 32, n0 = blockIdx.y * 32;
    const int z = blockIdx.z;
    const float* W = (z == 0) ? Wq : (z == 1) ? Wk : (z == 2) ? Wv : Wo;
    const int tid = threadIdx.x;

    #pragma unroll
    for (int it = 0; it < 4; it++) {
        int idx = tid + it * 256;
        int kk = idx >> 5, nn = idx & 31;
        float v;
        if (z < 3) {
            int n = n0 + nn, h = n >> 6, d = n & 63;
            v = W[((size_t)h * Ee + (k0 + kk)) * Dd + d];
        } else {
            v = W[(size_t)(k0 + kk) * Ee + (n0 + nn)];
        }
        t[kk][nn] = v;
    }
    __syncthreads();

    uint32_t* hi = g_Wh + (size_t)z * Ee * KP;
    uint32_t* lo = g_Wl + (size_t)z * Ee * KP;
    #pragma unroll
    for (int it = 0; it < 2; it++) {
        int idx = tid + it * 256;
        int nn = idx >> 4, kp = idx & 15;
        uint32_t h, l;
        split2(t[2 * kp][nn], t[2 * kp + 1][nn], h, l);
        size_t o = (size_t)(n0 + nn) * KP + (k0 >> 1) + kp;
        hi[o] = h; lo[o] = l;
    }
}

// ---------------------------------------------------------------------------
// Kernel 0b: x pre-pack (no transpose, row-major kp-minor).
// ---------------------------------------------------------------------------
__global__ __launch_bounds__(256) void pack_x(const float* __restrict__ x)
{
    int idx = blockIdx.x * 256 + threadIdx.x;
    float4 v = ((const float4*)x)[idx];
    uint32_t h0, l0, h1, l1;
    split2(v.x, v.y, h0, l0);
    split2(v.z, v.w, h1, l1);
    ((uint2*)g_Xh)[idx] = make_uint2(h0, h1);
    ((uint2*)g_Xl)[idx] = make_uint2(l0, l1);
}

// ---------------------------------------------------------------------------
// 2-split bf16 GEMM, CTA 128x128x32, 8 warps, cp.async 2-stage pipeline,
// 2 CTAs/SM, ldmatrix fragment loads. acc += Ah*Bh + Ah*Bl + Al*Bh.
// ---------------------------------------------------------------------------
constexpr int BM = 128, BN = 128, BK = 32;
constexpr int PSTRIDE = 20;
constexpr int PBUF = 128 * PSTRIDE;               // 2560 u32
constexpr int GEMM_SMEM_BYTES = 8 * PBUF * 4;     // 81920 B
constexpr int NKT = Ee / BK;                      // 32

__device__ __forceinline__ void gemm_compute_bf16(
    uint32_t sAbase, uint32_t sBbase, int buf, int wm, int wn, int lane,
    float acc[4][4][4])
{
    const uint32_t aHi = sAbase + buf * PBUF * 4;
    const uint32_t aLo = aHi + 2 * PBUF * 4;
    const uint32_t bHi = sBbase + buf * PBUF * 4;
    const uint32_t bLo = bHi + 2 * PBUF * 4;
    const int mIdx = lane >> 3, lr = lane & 7;
    // ldmatrix per-lane row/col offsets:
    //  A frags: M0 rows+klo, M1 rows+8+klo, M2 rows+khi, M3 rows+8+khi
    const int arow = (mIdx & 1) * 8 + lr, acol = (mIdx >> 1) * 4;
    //  B frags: M0 n+klo, M1 n+khi, M2 n+8+klo, M3 n+8+khi
    const int brow = (mIdx >> 1) * 8 + lr, bcol = (mIdx & 1) * 4;

    #pragma unroll
    for (int s = 0; s < 2; s++) {
        const int cb = 8 * s;
        uint32_t bh_[4][2], bl_[4][2];
        #pragma unroll
        for (int p = 0; p < 2; p++) {
            uint32_t off = (uint32_t)(((wn * 32 + p * 16 + brow) * PSTRIDE)
                                      + cb + bcol) * 4;
            ldsm_x4(bh_[2 * p][0], bh_[2 * p][1],
                    bh_[2 * p + 1][0], bh_[2 * p + 1][1], bHi + off);
            ldsm_x4(bl_[2 * p][0], bl_[2 * p][1],
                    bl_[2 * p + 1][0], bl_[2 * p + 1][1], bLo + off);
        }
        #pragma unroll
        for (int mt = 0; mt < 4; mt++) {
            uint32_t off = (uint32_t)(((wm * 64 + mt * 16 + arow) * PSTRIDE)
                                      + cb + acol) * 4;
            uint32_t ah0, ah1, ah2, ah3, al0, al1, al2, al3;
            ldsm_x4(ah0, ah1, ah2, ah3, aHi + off);
            ldsm_x4(al0, al1, al2, al3, aLo + off);
            #pragma unroll
            for (int nt = 0; nt < 4; nt++) {
                mma_bf16(acc[mt][nt], ah0, ah1, ah2, ah3, bh_[nt][0], bh_[nt][1]);
                mma_bf16(acc[mt][nt], ah0, ah1, ah2, ah3, bl_[nt][0], bl_[nt][1]);
                mma_bf16(acc[mt][nt], al0, al1, al2, al3, bh_[nt][0], bh_[nt][1]);
            }
        }
    }
}

__device__ __forceinline__ void gemm_issue(
    uint32_t sA, uint32_t sB, int buf, int kt, int tid, int m0, int n0,
    const uint32_t* gAh, const uint32_t* gAl,
    const uint32_t* gBh, const uint32_t* gBl)
{
    #pragma unroll
    for (int i = 0; i < 2; i++) {
        int f = tid + i * 256;
        int row = f >> 2, c4 = f & 3;
        uint32_t dA = sA + (buf * PBUF + row * PSTRIDE + c4 * 4) * 4;
        size_t oa = (size_t)(m0 + row) * KP + kt * 16 + c4 * 4;
        cp16(dA, gAh + oa);
        cp16(dA + 2 * PBUF * 4, gAl + oa);
        uint32_t dB = sB + (buf * PBUF + row * PSTRIDE + c4 * 4) * 4;
        size_t ob = (size_t)(n0 + row) * KP + kt * 16 + c4 * 4;
        cp16(dB, gBh + ob);
        cp16(dB + 2 * PBUF * 4, gBl + ob);
    }
    cp_commit();
}

// ---------------------------------------------------------------------------
// Kernel 1: fused QKV projection. Output RNA-rounded to tf32 precision.
// ---------------------------------------------------------------------------
__global__ __launch_bounds__(256, 2) void proj_qkv_tc(
    const float* __restrict__ bq, const float* __restrict__ bk,
    const float* __restrict__ bv)
{
    extern __shared__ uint32_t sm[];
    const int tid = threadIdx.x;
    const int lane = tid & 31, wid = tid >> 5;
    const int wm = wid >> 2, wn = wid & 3;
    const int g = lane >> 2, tig = lane & 3;

    const int z = blockIdx.z;
    const float* bias = (z == 0) ? bq : (z == 1) ? bk : bv;
    float* out = (z == 0) ? g_Q : (z == 1) ? g_K : g_V;
    const uint32_t* gBh = g_Wh + (size_t)z * Ee * KP;
    const uint32_t* gBl = g_Wl + (size_t)z * Ee * KP;

    const int m0 = blockIdx.x * BM;
    const int n0 = blockIdx.y * BN;

    uint32_t sA = (uint32_t)__cvta_generic_to_shared(sm);
    uint32_t sB = sA + 4 * PBUF * 4;

    float acc[4][4][4];
    #pragma unroll
    for (int mt = 0; mt < 4; mt++)
        #pragma unroll
        for (int nt = 0; nt < 4; nt++)
            #pragma unroll
            for (int v = 0; v < 4; v++) acc[mt][nt][v] = 0.f;

    gemm_issue(sA, sB, 0, 0, tid, m0, n0, g_Xh, g_Xl, gBh, gBl);
    gemm_issue(sA, sB, 1, 1, tid, m0, n0, g_Xh, g_Xl, gBh, gBl);

    int buf = 0;
    for (int kt = 0; kt < NKT; kt++) {
        if (kt + 1 < NKT) cp_wait<1>(); else cp_wait<0>();
        __syncthreads();
        gemm_compute_bf16(sA, sB, buf, wm, wn, lane, acc);
        __syncthreads();
        if (kt + 2 < NKT)
            gemm_issue(sA, sB, buf, kt + 2, tid, m0, n0, g_Xh, g_Xl, gBh, gBl);
        buf ^= 1;
    }

    // Epilogue: bias + RNA-round to tf32 + scatter to [B,H,S,D]
    #pragma unroll
    for (int mt = 0; mt < 4; mt++) {
        #pragma unroll
        for (int nt = 0; nt < 4; nt++) {
            int col = n0 + wn * 32 + nt * 8 + tig * 2;
            int h = col >> 6, d = col & 63;
            float b0 = bias[h * Dd + d], b1 = bias[h * Dd + d + 1];
            int m = m0 + wm * 64 + mt * 16 + g;
            #pragma unroll
            for (int rr = 0; rr < 2; rr++) {
                int row = m + rr * 8;
                int b = row >> 11, s = row & 2047;
                float* o = out + (((size_t)(b * Hh + h)) * Ss + s) * Dd + d;
                o[0] = __uint_as_float(f2tf32(acc[mt][nt][rr * 2 + 0] + b0));
                o[1] = __uint_as_float(f2tf32(acc[mt][nt][rr * 2 + 1] + b1));
            }
        }
    }
}

// ---------------------------------------------------------------------------
// Kernel 3: output projection (reads packed attn output).
// ---------------------------------------------------------------------------
__global__ __launch_bounds__(256, 2) void out_proj_tc(float* __restrict__ out)
{
    extern __shared__ uint32_t sm[];
    const int tid = threadIdx.x;
    const int lane = tid & 31, wid = tid >> 5;
    const int wm = wid >> 2, wn = wid & 3;
    const int g = lane >> 2, tig = lane & 3;

    const uint32_t* gBh = g_Wh + (size_t)3 * Ee * KP;
    const uint32_t* gBl = g_Wl + (size_t)3 * Ee * KP;

    const int m0 = blockIdx.x * BM;
    const int n0 = blockIdx.y * BN;

    uint32_t sA = (uint32_t)__cvta_generic_to_shared(sm);
    uint32_t sB = sA + 4 * PBUF * 4;

    float acc[4][4][4];
    #pragma unroll
    for (int mt = 0; mt < 4; mt++)
        #pragma unroll
        for (int nt = 0; nt < 4; nt++)
            #pragma unroll
            for (int v = 0; v < 4; v++) acc[mt][nt][v] = 0.f;

    gemm_issue(sA, sB, 0, 0, tid, m0, n0, g_AOh, g_AOl, gBh, gBl);
    gemm_issue(sA, sB, 1, 1, tid, m0, n0, g_AOh, g_AOl, gBh, gBl);

    int buf = 0;
    for (int kt = 0; kt < NKT; kt++) {
        if (kt + 1 < NKT) cp_wait<1>(); else cp_wait<0>();
        __syncthreads();
        gemm_compute_bf16(sA, sB, buf, wm, wn, lane, acc);
        __syncthreads();
        if (kt + 2 < NKT)
            gemm_issue(sA, sB, buf, kt + 2, tid, m0, n0, g_AOh, g_AOl, gBh, gBl);
        buf ^= 1;
    }

    #pragma unroll
    for (int mt = 0; mt < 4; mt++) {
        #pragma unroll
        for (int nt = 0; nt < 4; nt++) {
            int col = n0 + wn * 32 + nt * 8 + tig * 2;
            int m = m0 + wm * 64 + mt * 16 + g;
            #pragma unroll
            for (int rr = 0; rr < 2; rr++) {
                int row = m + rr * 8;
                out[(size_t)row * Ee + col]     = acc[mt][nt][rr * 2 + 0];
                out[(size_t)row * Ee + col + 1] = acc[mt][nt][rr * 2 + 1];
            }
        }
    }
}

// ---------------------------------------------------------------------------
// Kernel 2: causal flash attention, tf32 MMA, cp.async double-buffered K/V,
// ldmatrix fragment loads for Q/K/P. Inputs pre-rounded to tf32 in global.
// ---------------------------------------------------------------------------
constexpr int PSTR = 68;
constexpr int KSTR = 68;
constexpr int VSTR = 72;
constexpr int ATTN_SMEM_BYTES =
    (128 * PSTR + 2 * 64 * KSTR + 2 * 64 * VSTR) * 4;  // 106496 B

__global__ __launch_bounds__(256, 1) void attn_tc()
{
    extern __shared__ uint32_t smu[];
    uint32_t* Ps = smu;                             // [128][68]
    uint32_t* Ks = smu + 128 * PSTR;                // [2][64][68]
    uint32_t* Vs = Ks + 2 * 64 * KSTR;              // [2][64][72]

    const int qt = 15 - (int)blockIdx.x;
    const int bh = blockIdx.y;
    const int q0 = qt * 128;
    const int ntiles = 2 * qt + 2;

    const float* Qg = g_Q + (size_t)bh * Ss * Dd;
    const float* Kg = g_K + (size_t)bh * Ss * Dd;
    const float* Vg = g_V + (size_t)bh * Ss * Dd;

    const int tid = threadIdx.x;
    const int lane = tid & 31;
    const int w = tid >> 5;
    const int g = lane >> 2;
    const int tig = lane & 3;
    const int w16 = w * 16;
    const int mIdx = lane >> 3, lr = lane & 7;
    // ldmatrix lane offsets (A-pattern for P/Q, B-pattern for K)
    const int parow = (mIdx & 1) * 8 + lr, pacol = (mIdx >> 1) * 4;
    const int kbrow = (mIdx >> 1) * 8 + lr, kbcol = (mIdx & 1) * 4;

    const uint32_t sP = (uint32_t)__cvta_generic_to_shared(Ps);
    const uint32_t sK = (uint32_t)__cvta_generic_to_shared(Ks);
    const uint32_t sV = (uint32_t)__cvta_generic_to_shared(Vs);

    auto issue_kv = [&](int t, int b) {
        const int k0 = t * 64;
        #pragma unroll
        for (int i = 0; i < 4; i++) {
            int f = tid + i * 256;
            int r = f >> 4, c4 = f & 15;
            cp16(sK + (b * 64 * KSTR + r * KSTR + c4 * 4) * 4,
                 Kg + (size_t)(k0 + r) * Dd + c4 * 4);
            cp16(sV + (b * 64 * VSTR + r * VSTR + c4 * 4) * 4,
                 Vg + (size_t)(k0 + r) * Dd + c4 * 4);
        }
        cp_commit();
    };

    issue_kv(0, 0);
    if (ntiles > 1) issue_kv(1, 1);

    // Stage Q tile (already tf32-rounded in global)
    #pragma unroll
    for (int i = 0; i < 8; i++) {
        int f = tid + i * 256;
        int r = f >> 4, c4 = f & 15;
        float4 v = *(const float4*)(Qg + (size_t)(q0 + r) * Dd + c4 * 4);
        *(uint4*)(Ps + r * PSTR + c4 * 4) =
            make_uint4(__float_as_uint(v.x), __float_as_uint(v.y),
                       __float_as_uint(v.z), __float_as_uint(v.w));
    }
    __syncthreads();

    // Extract Q fragments via ldmatrix
    uint32_t qf[8][4];
    #pragma unroll
    for (int kk = 0; kk < 8; kk++) {
        uint32_t addr = sP + (uint32_t)((w16 + parow) * PSTR + kk * 8 + pacol) * 4;
        ldsm_x4(qf[kk][0], qf[kk][1], qf[kk][2], qf[kk][3], addr);
    }

    float oacc[8][4];
    #pragma unroll
    for (int nf = 0; nf < 8; nf++)
        #pragma unroll
        for (int v = 0; v < 4; v++) oacc[nf][v] = 0.f;
    float mrow[2] = {-1e30f, -1e30f};
    float lrow[2] = {0.f, 0.f};
    const float scale = 0.125f;

    int buf = 0;
    for (int t = 0; t < ntiles; t++) {
        if (t + 1 < ntiles) cp_wait<1>(); else cp_wait<0>();
        __syncthreads();

        const uint32_t sKb = sK + (uint32_t)(buf * 64 * KSTR) * 4;
        const uint32_t* Vb = Vs + buf * 64 * VSTR;

        // S = Q @ K^T (K B-frags via ldmatrix: 4 per kk cover nf pairs)
        float sacc[8][4];
        #pragma unroll
        for (int nf = 0; nf < 8; nf++)
            #pragma unroll
            for (int v = 0; v < 4; v++) sacc[nf][v] = 0.f;

        #pragma unroll
        for (int kk = 0; kk < 8; kk++) {
            #pragma unroll
            for (int p = 0; p < 4; p++) {
                uint32_t addr = sKb +
                    (uint32_t)((p * 16 + kbrow) * KSTR + kk * 8 + kbcol) * 4;
                uint32_t b0a, b1a, b0b, b1b;
                ldsm_x4(b0a, b1a, b0b, b1b, addr);
                mma_tf32(sacc[2 * p], qf[kk][0], qf[kk][1], qf[kk][2],
                         qf[kk][3], b0a, b1a);
                mma_tf32(sacc[2 * p + 1], qf[kk][0], qf[kk][1], qf[kk][2],
                         qf[kk][3], b0b, b1b);
            }
        }

        const int kv0 = t * 64;
        const bool domask = (t >= ntiles - 2);

        // Online softmax
        #pragma unroll
        for (int r = 0; r < 2; r++) {
            const int rowg = q0 + w16 + g + 8 * r;
            float mt = -1e30f;
            #pragma unroll
            for (int nf = 0; nf < 8; nf++) {
                float s0 = sacc[nf][2 * r]     * scale;
                float s1 = sacc[nf][2 * r + 1] * scale;
                if (domask) {
                    int col = kv0 + nf * 8 + 2 * tig;
                    if (col > rowg)     s0 = -1e30f;
                    if (col + 1 > rowg) s1 = -1e30f;
                }
                sacc[nf][2 * r] = s0; sacc[nf][2 * r + 1] = s1;
                mt = fmaxf(mt, fmaxf(s0, s1));
            }
            mt = fmaxf(mt, __shfl_xor_sync(0xffffffffu, mt, 1, 4));
            mt = fmaxf(mt, __shfl_xor_sync(0xffffffffu, mt, 2, 4));
            float mnew = fmaxf(mrow[r], mt);
            float corr = __expf(mrow[r] - mnew);
            float rs = 0.f;
            #pragma unroll
            for (int nf = 0; nf < 8; nf++) {
                float p0 = __expf(sacc[nf][2 * r] - mnew);
                float p1 = __expf(sacc[nf][2 * r + 1] - mnew);
                rs += p0 + p1;
                uint32_t* pp = Ps + (w16 + g + 8 * r) * PSTR + nf * 8 + 2 * tig;
                pp[0] = f2tf32(p0); pp[1] = f2tf32(p1);
            }
            rs += __shfl_xor_sync(0xffffffffu, rs, 1, 4);
            rs += __shfl_xor_sync(0xffffffffu, rs, 2, 4);
            lrow[r] = lrow[r] * corr + rs;
            mrow[r] = mnew;
            #pragma unroll
            for (int nf = 0; nf < 8; nf++) {
                oacc[nf][2 * r]     *= corr;
                oacc[nf][2 * r + 1] *= corr;
            }
        }
        __syncwarp();

        // O += P @ V (P A-frags via ldmatrix; V B-frags scalar LDS)
        #pragma unroll
        for (int kk = 0; kk < 8; kk++) {
            uint32_t addr = sP +
                (uint32_t)((w16 + parow) * PSTR + kk * 8 + pacol) * 4;
            uint32_t a0, a1, a2, a3;
            ldsm_x4(a0, a1, a2, a3, addr);
            #pragma unroll
            for (int nf = 0; nf < 8; nf++) {
                uint32_t b0 = Vb[(kk * 8 + tig) * VSTR + nf * 8 + g];
                uint32_t b1 = Vb[(kk * 8 + tig + 4) * VSTR + nf * 8 + g];
                mma_tf32(oacc[nf], a0, a1, a2, a3, b0, b1);
            }
        }

        __syncthreads();
        if (t + 2 < ntiles) issue_kv(t + 2, buf);
        buf ^= 1;
    }

    // Epilogue: normalize + write PACKED bf16 hi/lo [B*S][kp]
    const int b = bh >> 4, h = bh & 15;
    #pragma unroll
    for (int r = 0; r < 2; r++) {
        float inv = 1.0f / lrow[r];
        int s = q0 + w16 + g + 8 * r;
        size_t rowbase = (size_t)(b * Ss + s) * KP;
        #pragma unroll
        for (int nf = 0; nf < 8; nf++) {
            int d = nf * 8 + 2 * tig;
            float o0 = oacc[nf][2 * r] * inv;
            float o1 = oacc[nf][2 * r + 1] * inv;
            uint32_t hi, lo;
            split2(o0, o1, hi, lo);
            size_t off = rowbase + ((h * Dd + d) >> 1);
            g_AOh[off] = hi;
            g_AOl[off] = lo;
        }
    }
}

// ---------------------------------------------------------------------------
// Launch
// ---------------------------------------------------------------------------
extern "C" void kernel_launch(void* const* d_in, const int* in_sizes, int n_in,
                              void* d_out, int out_size)
{
    const float* x  = (const float*)d_in[0];
    const float* Wq = (const float*)d_in[1];
    const float* bq = (const float*)d_in[2];
    const float* Wk = (const float*)d_in[3];
    const float* bk = (const float*)d_in[4];
    const float* Wv = (const float*)d_in[5];
    const float* bv = (const float*)d_in[6];
    const float* Wo = (const float*)d_in[7];
    float* out = (float*)d_out;

    static bool attr_set = false;
    if (!attr_set) {
        cudaFuncSetAttribute(proj_qkv_tc,
            cudaFuncAttributeMaxDynamicSharedMemorySize, GEMM_SMEM_BYTES);
        cudaFuncSetAttribute(out_proj_tc,
            cudaFuncAttributeMaxDynamicSharedMemorySize, GEMM_SMEM_BYTES);
        cudaFuncSetAttribute(attn_tc,
            cudaFuncAttributeMaxDynamicSharedMemorySize, ATTN_SMEM_BYTES);
        attr_set = true;
    }

    // Pre-pack weights and x
    prep_pack<<<dim3(32, 32, 4), 256>>>(Wq, Wk, Wv, Wo);
    pack_x<<<dim3(Bb * Ss * Ee / 4 / 256), 256>>>(x);

    // QKV projections
    proj_qkv_tc<<<dim3(32, 8, 3), 256, GEMM_SMEM_BYTES>>>(bq, bk, bv);

    // Flash attention
    attn_tc<<<dim3(16, Bb * Hh), 256, ATTN_SMEM_BYTES>>>();

    // Output projection
    out_proj_tc<<<dim3(32, 8), 256, GEMM_SMEM_BYTES>>>(out);
}

// round 9
// speedup vs baseline: 3.3936x; 1.0054x over previous
#include <cuda_runtime.h>
#include <cuda_bf16.h>
#include <math.h>
#include <stdint.h>

// Problem constants
constexpr int Bb = 2;
constexpr int Ss = 2048;
constexpr int Ee = 1024;
constexpr int Hh = 16;
constexpr int Dd = 64;
constexpr int KP = Ee / 2;   // packed u32 (bf16x2) per row

// Scratch (device globals — no allocation allowed)
// g_Q holds values pre-scaled by 0.125*log2(e) and RNA-rounded to tf32.
// g_K/g_V hold values RNA-rounded to tf32.
__device__ float g_Q[(size_t)Bb * Hh * Ss * Dd];   // [B,H,S,D]
__device__ float g_K[(size_t)Bb * Hh * Ss * Dd];
__device__ float g_V[(size_t)Bb * Hh * Ss * Dd];
// Pre-packed bf16 hi/lo operands (u32 = 2 bf16, k-pairs minor)
__device__ uint32_t g_Wh[(size_t)4 * Ee * KP];     // weights, [z][n][kp]
__device__ uint32_t g_Wl[(size_t)4 * Ee * KP];
__device__ uint32_t g_Xh[(size_t)Bb * Ss * KP];    // x, [row][kp]
__device__ uint32_t g_Xl[(size_t)Bb * Ss * KP];
__device__ uint32_t g_AOh[(size_t)Bb * Ss * KP];   // attn out, [row][kp]
__device__ uint32_t g_AOl[(size_t)Bb * Ss * KP];

// ---------------------------------------------------------------------------
// Helpers
// ---------------------------------------------------------------------------
__device__ __forceinline__ uint32_t f2tf32(float f) {
    uint32_t u;
    asm("cvt.rna.tf32.f32 %0, %1;" : "=r"(u) : "f"(f));
    return u;
}

__device__ __forceinline__ float fast_exp2(float x) {
    float y;
    asm("ex2.approx.f32 %0, %1;" : "=f"(y) : "f"(x));
    return y;
}

__device__ __forceinline__ uint32_t pack_bf16x2(float e_even, float e_odd) {
    uint32_t r;
    asm("cvt.rn.bf16x2.f32 %0, %1, %2;" : "=r"(r) : "f"(e_odd), "f"(e_even));
    return r;
}

__device__ __forceinline__ void split2(float v0, float v1,
                                       uint32_t& hi, uint32_t& lo) {
    float h0 = __bfloat162float(__float2bfloat16(v0));
    float h1 = __bfloat162float(__float2bfloat16(v1));
    hi = pack_bf16x2(h0, h1);
    lo = pack_bf16x2(v0 - h0, v1 - h1);
}

__device__ __forceinline__ void mma_tf32(float c[4], uint32_t a0, uint32_t a1,
                                         uint32_t a2, uint32_t a3,
                                         uint32_t b0, uint32_t b1) {
    asm volatile(
        "mma.sync.aligned.m16n8k8.row.col.f32.tf32.tf32.f32 "
        "{%0,%1,%2,%3}, {%4,%5,%6,%7}, {%8,%9}, {%0,%1,%2,%3};\n"
        : "+f"(c[0]), "+f"(c[1]), "+f"(c[2]), "+f"(c[3])
        : "r"(a0), "r"(a1), "r"(a2), "r"(a3), "r"(b0), "r"(b1));
}

__device__ __forceinline__ void mma_bf16(float c[4], uint32_t a0, uint32_t a1,
                                         uint32_t a2, uint32_t a3,
                                         uint32_t b0, uint32_t b1) {
    asm volatile(
        "mma.sync.aligned.m16n8k16.row.col.f32.bf16.bf16.f32 "
        "{%0,%1,%2,%3}, {%4,%5,%6,%7}, {%8,%9}, {%0,%1,%2,%3};\n"
        : "+f"(c[0]), "+f"(c[1]), "+f"(c[2]), "+f"(c[3])
        : "r"(a0), "r"(a1), "r"(a2), "r"(a3), "r"(b0), "r"(b1));
}

// ldmatrix x4: each lane supplies one 16B row address; 4 8x8(b16) matrices.
__device__ __forceinline__ void ldsm_x4(uint32_t& r0, uint32_t& r1,
                                        uint32_t& r2, uint32_t& r3,
                                        uint32_t saddr) {
    asm volatile(
        "ldmatrix.sync.aligned.m8n8.x4.shared.b16 {%0,%1,%2,%3}, [%4];"
        : "=r"(r0), "=r"(r1), "=r"(r2), "=r"(r3) : "r"(saddr));
}

__device__ __forceinline__ void cp16(uint32_t dst_smem, const void* src) {
    asm volatile("cp.async.cg.shared.global [%0], [%1], 16;"
                 :: "r"(dst_smem), "l"(src));
}
__device__ __forceinline__ void cp_commit() {
    asm volatile("cp.async.commit_group;");
}
template <int N>
__device__ __forceinline__ void cp_wait() {
    asm volatile("cp.async.wait_group %0;" :: "n"(N));
}

// ---------------------------------------------------------------------------
// Kernel 0: weight + x pre-pack. z<4: transpose W to [n][kpair], split hi/lo.
// z==4: pack x rows (no transpose). Fused to save a launch.
// ---------------------------------------------------------------------------
__global__ __launch_bounds__(256) void prep_pack(
    const float* __restrict__ Wq, const float* __restrict__ Wk,
    const float* __restrict__ Wv, const float* __restrict__ Wo,
    const float* __restrict__ x)
{
    __shared__ float t[32][33];
    const int z = blockIdx.z;
    const int tid = threadIdx.x;

    if (z == 4) {
        // pack x: 1024 blocks (bx, by), 4 float4 per thread
        int blk = blockIdx.y * 32 + blockIdx.x;
        #pragma unroll
        for (int it = 0; it < 4; it++) {
            int idx = (blk * 4 + it) * 256 + tid;
            float4 v = ((const float4*)x)[idx];
            uint32_t h0, l0, h1, l1;
            split2(v.x, v.y, h0, l0);
            split2(v.z, v.w, h1, l1);
            ((uint2*)g_Xh)[idx] = make_uint2(h0, h1);
            ((uint2*)g_Xl)[idx] = make_uint2(l0, l1);
        }
        return;
    }

    const int k0 = blockIdx.x * 32, n0 = blockIdx.y * 32;
    const float* W = (z == 0) ? Wq : (z == 1) ? Wk : (z == 2) ? Wv : Wo;

    #pragma unroll
    for (int it = 0; it < 4; it++) {
        int idx = tid + it * 256;
        int kk = idx >> 5, nn = idx & 31;
        float v;
        if (z < 3) {
            int n = n0 + nn, h = n >> 6, d = n & 63;
            v = W[((size_t)h * Ee + (k0 + kk)) * Dd + d];
        } else {
            v = W[(size_t)(k0 + kk) * Ee + (n0 + nn)];
        }
        t[kk][nn] = v;
    }
    __syncthreads();

    uint32_t* hi = g_Wh + (size_t)z * Ee * KP;
    uint32_t* lo = g_Wl + (size_t)z * Ee * KP;
    #pragma unroll
    for (int it = 0; it < 2; it++) {
        int idx = tid + it * 256;
        int nn = idx >> 4, kp = idx & 15;
        uint32_t h, l;
        split2(t[2 * kp][nn], t[2 * kp + 1][nn], h, l);
        size_t o = (size_t)(n0 + nn) * KP + (k0 >> 1) + kp;
        hi[o] = h; lo[o] = l;
    }
}

// ---------------------------------------------------------------------------
// 2-split bf16 GEMM, CTA 128x128x32, 8 warps, cp.async 2-stage pipeline,
// 2 CTAs/SM, ldmatrix fragment loads. acc += Ah*Bh + Ah*Bl + Al*Bh.
// ---------------------------------------------------------------------------
constexpr int BM = 128, BN = 128, BK = 32;
constexpr int PSTRIDE = 20;
constexpr int PBUF = 128 * PSTRIDE;               // 2560 u32
constexpr int GEMM_SMEM_BYTES = 8 * PBUF * 4;     // 81920 B
constexpr int NKT = Ee / BK;                      // 32

__device__ __forceinline__ void gemm_compute_bf16(
    uint32_t sAbase, uint32_t sBbase, int buf, int wm, int wn, int lane,
    float acc[4][4][4])
{
    const uint32_t aHi = sAbase + buf * PBUF * 4;
    const uint32_t aLo = aHi + 2 * PBUF * 4;
    const uint32_t bHi = sBbase + buf * PBUF * 4;
    const uint32_t bLo = bHi + 2 * PBUF * 4;
    const int mIdx = lane >> 3, lr = lane & 7;
    const int arow = (mIdx & 1) * 8 + lr, acol = (mIdx >> 1) * 4;
    const int brow = (mIdx >> 1) * 8 + lr, bcol = (mIdx & 1) * 4;

    #pragma unroll
    for (int s = 0; s < 2; s++) {
        const int cb = 8 * s;
        uint32_t bh_[4][2], bl_[4][2];
        #pragma unroll
        for (int p = 0; p < 2; p++) {
            uint32_t off = (uint32_t)(((wn * 32 + p * 16 + brow) * PSTRIDE)
                                      + cb + bcol) * 4;
            ldsm_x4(bh_[2 * p][0], bh_[2 * p][1],
                    bh_[2 * p + 1][0], bh_[2 * p + 1][1], bHi + off);
            ldsm_x4(bl_[2 * p][0], bl_[2 * p][1],
                    bl_[2 * p + 1][0], bl_[2 * p + 1][1], bLo + off);
        }
        #pragma unroll
        for (int mt = 0; mt < 4; mt++) {
            uint32_t off = (uint32_t)(((wm * 64 + mt * 16 + arow) * PSTRIDE)
                                      + cb + acol) * 4;
            uint32_t ah0, ah1, ah2, ah3, al0, al1, al2, al3;
            ldsm_x4(ah0, ah1, ah2, ah3, aHi + off);
            ldsm_x4(al0, al1, al2, al3, aLo + off);
            #pragma unroll
            for (int nt = 0; nt < 4; nt++) {
                mma_bf16(acc[mt][nt], ah0, ah1, ah2, ah3, bh_[nt][0], bh_[nt][1]);
                mma_bf16(acc[mt][nt], ah0, ah1, ah2, ah3, bl_[nt][0], bl_[nt][1]);
                mma_bf16(acc[mt][nt], al0, al1, al2, al3, bh_[nt][0], bh_[nt][1]);
            }
        }
    }
}

__device__ __forceinline__ void gemm_issue(
    uint32_t sA, uint32_t sB, int buf, int kt, int tid, int m0, int n0,
    const uint32_t* gAh, const uint32_t* gAl,
    const uint32_t* gBh, const uint32_t* gBl)
{
    #pragma unroll
    for (int i = 0; i < 2; i++) {
        int f = tid + i * 256;
        int row = f >> 2, c4 = f & 3;
        uint32_t dA = sA + (buf * PBUF + row * PSTRIDE + c4 * 4) * 4;
        size_t oa = (size_t)(m0 + row) * KP + kt * 16 + c4 * 4;
        cp16(dA, gAh + oa);
        cp16(dA + 2 * PBUF * 4, gAl + oa);
        uint32_t dB = sB + (buf * PBUF + row * PSTRIDE + c4 * 4) * 4;
        size_t ob = (size_t)(n0 + row) * KP + kt * 16 + c4 * 4;
        cp16(dB, gBh + ob);
        cp16(dB + 2 * PBUF * 4, gBl + ob);
    }
    cp_commit();
}

// ---------------------------------------------------------------------------
// Kernel 1: fused QKV projection. Q output is pre-scaled by 0.125*log2(e) and
// RNA-rounded; K/V outputs RNA-rounded.
// ---------------------------------------------------------------------------
__global__ __launch_bounds__(256, 2) void proj_qkv_tc(
    const float* __restrict__ bq, const float* __restrict__ bk,
    const float* __restrict__ bv)
{
    extern __shared__ uint32_t sm[];
    const int tid = threadIdx.x;
    const int lane = tid & 31, wid = tid >> 5;
    const int wm = wid >> 2, wn = wid & 3;
    const int g = lane >> 2, tig = lane & 3;

    const int z = blockIdx.z;
    const float* bias = (z == 0) ? bq : (z == 1) ? bk : bv;
    float* out = (z == 0) ? g_Q : (z == 1) ? g_K : g_V;
    const float oscale = (z == 0) ? 0.125f * 1.44269504089f : 1.0f;
    const uint32_t* gBh = g_Wh + (size_t)z * Ee * KP;
    const uint32_t* gBl = g_Wl + (size_t)z * Ee * KP;

    const int m0 = blockIdx.x * BM;
    const int n0 = blockIdx.y * BN;

    uint32_t sA = (uint32_t)__cvta_generic_to_shared(sm);
    uint32_t sB = sA + 4 * PBUF * 4;

    float acc[4][4][4];
    #pragma unroll
    for (int mt = 0; mt < 4; mt++)
        #pragma unroll
        for (int nt = 0; nt < 4; nt++)
            #pragma unroll
            for (int v = 0; v < 4; v++) acc[mt][nt][v] = 0.f;

    gemm_issue(sA, sB, 0, 0, tid, m0, n0, g_Xh, g_Xl, gBh, gBl);
    gemm_issue(sA, sB, 1, 1, tid, m0, n0, g_Xh, g_Xl, gBh, gBl);

    int buf = 0;
    for (int kt = 0; kt < NKT; kt++) {
        if (kt + 1 < NKT) cp_wait<1>(); else cp_wait<0>();
        __syncthreads();
        gemm_compute_bf16(sA, sB, buf, wm, wn, lane, acc);
        __syncthreads();
        if (kt + 2 < NKT)
            gemm_issue(sA, sB, buf, kt + 2, tid, m0, n0, g_Xh, g_Xl, gBh, gBl);
        buf ^= 1;
    }

    // Epilogue: bias + (optional scale) + RNA-round to tf32 + scatter
    #pragma unroll
    for (int mt = 0; mt < 4; mt++) {
        #pragma unroll
        for (int nt = 0; nt < 4; nt++) {
            int col = n0 + wn * 32 + nt * 8 + tig * 2;
            int h = col >> 6, d = col & 63;
            float b0 = bias[h * Dd + d], b1 = bias[h * Dd + d + 1];
            int m = m0 + wm * 64 + mt * 16 + g;
            #pragma unroll
            for (int rr = 0; rr < 2; rr++) {
                int row = m + rr * 8;
                int b = row >> 11, s = row & 2047;
                float* o = out + (((size_t)(b * Hh + h)) * Ss + s) * Dd + d;
                o[0] = __uint_as_float(
                    f2tf32((acc[mt][nt][rr * 2 + 0] + b0) * oscale));
                o[1] = __uint_as_float(
                    f2tf32((acc[mt][nt][rr * 2 + 1] + b1) * oscale));
            }
        }
    }
}

// ---------------------------------------------------------------------------
// Kernel 3: output projection (reads packed attn output).
// ---------------------------------------------------------------------------
__global__ __launch_bounds__(256, 2) void out_proj_tc(float* __restrict__ out)
{
    extern __shared__ uint32_t sm[];
    const int tid = threadIdx.x;
    const int lane = tid & 31, wid = tid >> 5;
    const int wm = wid >> 2, wn = wid & 3;
    const int g = lane >> 2, tig = lane & 3;

    const uint32_t* gBh = g_Wh + (size_t)3 * Ee * KP;
    const uint32_t* gBl = g_Wl + (size_t)3 * Ee * KP;

    const int m0 = blockIdx.x * BM;
    const int n0 = blockIdx.y * BN;

    uint32_t sA = (uint32_t)__cvta_generic_to_shared(sm);
    uint32_t sB = sA + 4 * PBUF * 4;

    float acc[4][4][4];
    #pragma unroll
    for (int mt = 0; mt < 4; mt++)
        #pragma unroll
        for (int nt = 0; nt < 4; nt++)
            #pragma unroll
            for (int v = 0; v < 4; v++) acc[mt][nt][v] = 0.f;

    gemm_issue(sA, sB, 0, 0, tid, m0, n0, g_AOh, g_AOl, gBh, gBl);
    gemm_issue(sA, sB, 1, 1, tid, m0, n0, g_AOh, g_AOl, gBh, gBl);

    int buf = 0;
    for (int kt = 0; kt < NKT; kt++) {
        if (kt + 1 < NKT) cp_wait<1>(); else cp_wait<0>();
        __syncthreads();
        gemm_compute_bf16(sA, sB, buf, wm, wn, lane, acc);
        __syncthreads();
        if (kt + 2 < NKT)
            gemm_issue(sA, sB, buf, kt + 2, tid, m0, n0, g_AOh, g_AOl, gBh, gBl);
        buf ^= 1;
    }

    #pragma unroll
    for (int mt = 0; mt < 4; mt++) {
        #pragma unroll
        for (int nt = 0; nt < 4; nt++) {
            int col = n0 + wn * 32 + nt * 8 + tig * 2;
            int m = m0 + wm * 64 + mt * 16 + g;
            #pragma unroll
            for (int rr = 0; rr < 2; rr++) {
                int row = m + rr * 8;
                out[(size_t)row * Ee + col]     = acc[mt][nt][rr * 2 + 0];
                out[(size_t)row * Ee + col + 1] = acc[mt][nt][rr * 2 + 1];
            }
        }
    }
}

// ---------------------------------------------------------------------------
// Kernel 2: causal flash attention. q-tile 128, KV tile 128, double-buffered
// cp.async, tf32 MMA, base-2 softmax (Q pre-scaled), ldmatrix frags.
// ---------------------------------------------------------------------------
constexpr int QSTR = 132;   // P/Q region stride (u32)
constexpr int KSTR = 68;
constexpr int VSTR = 72;
constexpr int ATTN_SMEM_BYTES =
    (128 * QSTR + 2 * 128 * KSTR + 2 * 128 * VSTR) * 4;  // 210944 B

__global__ __launch_bounds__(256, 1) void attn_tc()
{
    extern __shared__ uint32_t smu[];
    uint32_t* Ps = smu;                             // [128][132]  Q then P
    uint32_t* Ks = smu + 128 * QSTR;                // [2][128][68]
    uint32_t* Vs = Ks + 2 * 128 * KSTR;             // [2][128][72]

    const int qt = 15 - (int)blockIdx.x;            // heavy first
    const int bh = blockIdx.y;
    const int q0 = qt * 128;
    const int ntiles = qt + 1;                      // KV tiles of 128

    const float* Qg = g_Q + (size_t)bh * Ss * Dd;
    const float* Kg = g_K + (size_t)bh * Ss * Dd;
    const float* Vg = g_V + (size_t)bh * Ss * Dd;

    const int tid = threadIdx.x;
    const int lane = tid & 31;
    const int w = tid >> 5;
    const int g = lane >> 2;
    const int tig = lane & 3;
    const int w16 = w * 16;
    const int mIdx = lane >> 3, lr = lane & 7;
    const int parow = (mIdx & 1) * 8 + lr, pacol = (mIdx >> 1) * 4;
    const int kbrow = (mIdx >> 1) * 8 + lr, kbcol = (mIdx & 1) * 4;

    const uint32_t sP = (uint32_t)__cvta_generic_to_shared(Ps);
    const uint32_t sK = (uint32_t)__cvta_generic_to_shared(Ks);
    const uint32_t sV = (uint32_t)__cvta_generic_to_shared(Vs);

    auto issue_kv = [&](int t, int b) {
        const int k0 = t * 128;
        #pragma unroll
        for (int i = 0; i < 8; i++) {
            int f = tid + i * 256;
            int r = f >> 4, c4 = f & 15;
            cp16(sK + (b * 128 * KSTR + r * KSTR + c4 * 4) * 4,
                 Kg + (size_t)(k0 + r) * Dd + c4 * 4);
            cp16(sV + (b * 128 * VSTR + r * VSTR + c4 * 4) * 4,
                 Vg + (size_t)(k0 + r) * Dd + c4 * 4);
        }
        cp_commit();
    };

    issue_kv(0, 0);
    if (ntiles > 1) issue_kv(1, 1);

    // Stage Q tile (pre-scaled, tf32-rounded in global) into Ps
    #pragma unroll
    for (int i = 0; i < 8; i++) {
        int f = tid + i * 256;
        int r = f >> 4, c4 = f & 15;
        float4 v = *(const float4*)(Qg + (size_t)(q0 + r) * Dd + c4 * 4);
        *(uint4*)(Ps + r * QSTR + c4 * 4) =
            make_uint4(__float_as_uint(v.x), __float_as_uint(v.y),
                       __float_as_uint(v.z), __float_as_uint(v.w));
    }
    __syncthreads();

    // Extract Q fragments via ldmatrix (once; Ps then becomes P store)
    uint32_t qf[8][4];
    #pragma unroll
    for (int kk = 0; kk < 8; kk++) {
        uint32_t addr = sP + (uint32_t)((w16 + parow) * QSTR + kk * 8 + pacol) * 4;
        ldsm_x4(qf[kk][0], qf[kk][1], qf[kk][2], qf[kk][3], addr);
    }

    float oacc[8][4];
    #pragma unroll
    for (int nf = 0; nf < 8; nf++)
        #pragma unroll
        for (int v = 0; v < 4; v++) oacc[nf][v] = 0.f;
    float mrow[2] = {-1e30f, -1e30f};
    float lrow[2] = {0.f, 0.f};

    int buf = 0;
    for (int t = 0; t < ntiles; t++) {
        if (t + 1 < ntiles) cp_wait<1>(); else cp_wait<0>();
        __syncthreads();

        const uint32_t sKb = sK + (uint32_t)(buf * 128 * KSTR) * 4;
        const uint32_t* Vb = Vs + buf * 128 * VSTR;

        // S = Q @ K^T over 128 kv cols (scores already in log2 domain)
        float sacc[16][4];
        #pragma unroll
        for (int nf = 0; nf < 16; nf++)
            #pragma unroll
            for (int v = 0; v < 4; v++) sacc[nf][v] = 0.f;

        #pragma unroll
        for (int kk = 0; kk < 8; kk++) {
            #pragma unroll
            for (int p = 0; p < 8; p++) {
                uint32_t addr = sKb +
                    (uint32_t)((p * 16 + kbrow) * KSTR + kk * 8 + kbcol) * 4;
                uint32_t b0a, b1a, b0b, b1b;
                ldsm_x4(b0a, b1a, b0b, b1b, addr);
                mma_tf32(sacc[2 * p], qf[kk][0], qf[kk][1], qf[kk][2],
                         qf[kk][3], b0a, b1a);
                mma_tf32(sacc[2 * p + 1], qf[kk][0], qf[kk][1], qf[kk][2],
                         qf[kk][3], b0b, b1b);
            }
        }

        const int kv0 = t * 128;
        const bool domask = (t == ntiles - 1);   // only diagonal tile

        // Online softmax (base-2)
        #pragma unroll
        for (int r = 0; r < 2; r++) {
            const int rowg = q0 + w16 + g + 8 * r;
            float mt = -1e30f;
            #pragma unroll
            for (int nf = 0; nf < 16; nf++) {
                float s0 = sacc[nf][2 * r];
                float s1 = sacc[nf][2 * r + 1];
                if (domask) {
                    int col = kv0 + nf * 8 + 2 * tig;
                    if (col > rowg)     s0 = -1e30f;
                    if (col + 1 > rowg) s1 = -1e30f;
                }
                sacc[nf][2 * r] = s0; sacc[nf][2 * r + 1] = s1;
                mt = fmaxf(mt, fmaxf(s0, s1));
            }
            mt = fmaxf(mt, __shfl_xor_sync(0xffffffffu, mt, 1, 4));
            mt = fmaxf(mt, __shfl_xor_sync(0xffffffffu, mt, 2, 4));
            float mnew = fmaxf(mrow[r], mt);
            float corr = fast_exp2(mrow[r] - mnew);
            float rs = 0.f;
            #pragma unroll
            for (int nf = 0; nf < 16; nf++) {
                float p0 = fast_exp2(sacc[nf][2 * r] - mnew);
                float p1 = fast_exp2(sacc[nf][2 * r + 1] - mnew);
                rs += p0 + p1;
                *(uint2*)(Ps + (w16 + g + 8 * r) * QSTR + nf * 8 + 2 * tig) =
                    make_uint2(f2tf32(p0), f2tf32(p1));
            }
            rs += __shfl_xor_sync(0xffffffffu, rs, 1, 4);
            rs += __shfl_xor_sync(0xffffffffu, rs, 2, 4);
            lrow[r] = lrow[r] * corr + rs;
            mrow[r] = mnew;
            #pragma unroll
            for (int nf = 0; nf < 8; nf++) {
                oacc[nf][2 * r]     *= corr;
                oacc[nf][2 * r + 1] *= corr;
            }
        }
        __syncwarp();

        // O += P @ V over k=128 (P A-frags via ldmatrix; V scalar LDS)
        #pragma unroll
        for (int kk = 0; kk < 16; kk++) {
            uint32_t addr = sP +
                (uint32_t)((w16 + parow) * QSTR + kk * 8 + pacol) * 4;
            uint32_t a0, a1, a2, a3;
            ldsm_x4(a0, a1, a2, a3, addr);
            #pragma unroll
            for (int nf = 0; nf < 8; nf++) {
                uint32_t b0 = Vb[(kk * 8 + tig) * VSTR + nf * 8 + g];
                uint32_t b1 = Vb[(kk * 8 + tig + 4) * VSTR + nf * 8 + g];
                mma_tf32(oacc[nf], a0, a1, a2, a3, b0, b1);
            }
        }

        __syncthreads();
        if (t + 2 < ntiles) issue_kv(t + 2, buf);
        buf ^= 1;
    }

    // Epilogue: normalize + write PACKED bf16 hi/lo [B*S][kp]
    const int b = bh >> 4, h = bh & 15;
    #pragma unroll
    for (int r = 0; r < 2; r++) {
        float inv = 1.0f / lrow[r];
        int s = q0 + w16 + g + 8 * r;
        size_t rowbase = (size_t)(b * Ss + s) * KP;
        #pragma unroll
        for (int nf = 0; nf < 8; nf++) {
            int d = nf * 8 + 2 * tig;
            float o0 = oacc[nf][2 * r] * inv;
            float o1 = oacc[nf][2 * r + 1] * inv;
            uint32_t hi, lo;
            split2(o0, o1, hi, lo);
            size_t off = rowbase + ((h * Dd + d) >> 1);
            g_AOh[off] = hi;
            g_AOl[off] = lo;
        }
    }
}

// ---------------------------------------------------------------------------
// Launch
// ---------------------------------------------------------------------------
extern "C" void kernel_launch(void* const* d_in, const int* in_sizes, int n_in,
                              void* d_out, int out_size)
{
    const float* x  = (const float*)d_in[0];
    const float* Wq = (const float*)d_in[1];
    const float* bq = (const float*)d_in[2];
    const float* Wk = (const float*)d_in[3];
    const float* bk = (const float*)d_in[4];
    const float* Wv = (const float*)d_in[5];
    const float* bv = (const float*)d_in[6];
    const float* Wo = (const float*)d_in[7];
    float* out = (float*)d_out;

    static bool attr_set = false;
    if (!attr_set) {
        cudaFuncSetAttribute(proj_qkv_tc,
            cudaFuncAttributeMaxDynamicSharedMemorySize, GEMM_SMEM_BYTES);
        cudaFuncSetAttribute(out_proj_tc,
            cudaFuncAttributeMaxDynamicSharedMemorySize, GEMM_SMEM_BYTES);
        cudaFuncSetAttribute(attn_tc,
            cudaFuncAttributeMaxDynamicSharedMemorySize, ATTN_SMEM_BYTES);
        attr_set = true;
    }

    // Pre-pack weights (z 0..3) and x (z == 4)
    prep_pack<<<dim3(32, 32, 5), 256>>>(Wq, Wk, Wv, Wo, x);

    // QKV projections
    proj_qkv_tc<<<dim3(32, 8, 3), 256, GEMM_SMEM_BYTES>>>(bq, bk, bv);

    // Flash attention: 16 q-tiles x 32 (b,h)
    attn_tc<<<dim3(16, Bb * Hh), 256, ATTN_SMEM_BYTES>>>();

    // Output projection
    out_proj_tc<<<dim3(32, 8), 256, GEMM_SMEM_BYTES>>>(out);
}